// round 12
// baseline (speedup 1.0000x reference)
#include <cuda_runtime.h>
#include <cuda_fp16.h>
#include <cstdint>

// Problem shape (fixed by dataset)
#define B_  2
#define T_  2048
#define C_  1024
#define H_  16
#define HD_ 64
#define NI_ 3
#define M_  (B_ * T_)
#define NEG_ (-1e9f)

typedef __half f16;

// -------- scratch (device globals; no allocation allowed) --------
__device__ f16 g_Qh[(size_t)M_ * C_],       g_Ql[(size_t)M_ * C_];
__device__ f16 g_Kh[(size_t)M_ * C_];
__device__ f16 g_Vh[(size_t)M_ * C_];
__device__ f16 g_xqh[(size_t)M_ * C_],      g_xql[(size_t)M_ * C_];
__device__ f16 g_xrh[(size_t)M_ * C_],      g_xrl[(size_t)M_ * C_];
__device__ f16 g_yh [(size_t)NI_ * M_ * C_], g_yl [(size_t)NI_ * M_ * C_];
__device__ f16 g_Oh [(size_t)M_ * C_],      g_Ol [(size_t)M_ * C_];
__device__ f16 g_Wqh[(size_t)C_ * C_];
__device__ f16 g_Wkh[(size_t)C_ * C_];
__device__ f16 g_Wvh[(size_t)NI_ * C_ * C_];
__device__ f16 g_Wph[(size_t)C_ * C_];
__device__ float g_wm[(size_t)B_ * T_ * T_];  // mask? exp(-4d^2) : -1

// ============================================================================
// helpers
// ============================================================================
__device__ __forceinline__ uint32_t smem_u32(const void* p) {
    uint32_t a;
    asm("{ .reg .u64 t; cvta.to.shared.u64 t, %1; cvt.u32.u64 %0, t; }"
        : "=r"(a) : "l"(p));
    return a;
}
__device__ __forceinline__ uint32_t pack_h2(float a, float b) {
    f16 h0 = __float2half_rn(a);
    f16 h1 = __float2half_rn(b);
    return ((uint32_t)__half_as_ushort(h1) << 16) | __half_as_ushort(h0);
}
__device__ __forceinline__ void split2h(float a, float b, uint32_t& hi, uint32_t& lo) {
    f16 h0 = __float2half_rn(a);
    f16 h1 = __float2half_rn(b);
    hi = ((uint32_t)__half_as_ushort(h1) << 16) | __half_as_ushort(h0);
    lo = pack_h2(a - __half2float(h0), b - __half2float(h1));
}

#define CP_ASYNC16(dst, src) \
    asm volatile("cp.async.cg.shared.global [%0], [%1], 16;" :: "r"(dst), "l"(src))
#define CP_COMMIT() asm volatile("cp.async.commit_group;" ::: "memory")
#define CP_WAIT(n)  asm volatile("cp.async.wait_group %0;" :: "n"(n) : "memory")

#define LDSM_X4(r0, r1, r2, r3, addr) \
    asm volatile("ldmatrix.sync.aligned.m8n8.x4.shared.b16 {%0,%1,%2,%3}, [%4];" \
                 : "=r"(r0), "=r"(r1), "=r"(r2), "=r"(r3) : "r"(addr))
#define LDSM_X4T(r0, r1, r2, r3, addr) \
    asm volatile("ldmatrix.sync.aligned.m8n8.x4.trans.shared.b16 {%0,%1,%2,%3}, [%4];" \
                 : "=r"(r0), "=r"(r1), "=r"(r2), "=r"(r3) : "r"(addr))

#define MMA16816(d, a, b0, b1) \
    asm volatile("mma.sync.aligned.m16n8k16.row.col.f32.f16.f16.f32 " \
                 "{%0,%1,%2,%3}, {%4,%5,%6,%7}, {%8,%9}, {%0,%1,%2,%3};" \
                 : "+f"((d)[0]), "+f"((d)[1]), "+f"((d)[2]), "+f"((d)[3]) \
                 : "r"((a)[0]), "r"((a)[1]), "r"((a)[2]), "r"((a)[3]), \
                   "r"(b0), "r"(b1))

// ============================================================================
// split kernel: fp32 -> f16 hi + f16 lo (residual)
// ============================================================================
__global__ __launch_bounds__(256) void split_kernel(
    const float4* __restrict__ in, uint2* __restrict__ hi,
    uint2* __restrict__ lo, int n4)
{
    int i = blockIdx.x * 256 + threadIdx.x;
    if (i >= n4) return;
    float4 f = in[i];
    uint32_t h0, l0, h1, l1;
    split2h(f.x, f.y, h0, l0);
    split2h(f.z, f.w, h1, l1);
    hi[i] = make_uint2(h0, h1);
    lo[i] = make_uint2(l0, l1);
}

// quant kernel: fp32 -> single f16 (weights)
__global__ __launch_bounds__(256) void quant_kernel(
    const float4* __restrict__ in, uint2* __restrict__ hi, int n4)
{
    int i = blockIdx.x * 256 + threadIdx.x;
    if (i >= n4) return;
    float4 f = in[i];
    hi[i] = make_uint2(pack_h2(f.x, f.y), pack_h2(f.z, f.w));
}

// ============================================================================
// wm kernel: wm = mask ? exp(-4 d^2) : -1
// ============================================================================
__global__ __launch_bounds__(256) void wm_kernel(
    const int2* __restrict__ mask, const float2* __restrict__ dist,
    float2* __restrict__ wm, int n2)
{
    int i = blockIdx.x * 256 + threadIdx.x;
    if (i >= n2) return;
    int2 m = mask[i];
    float2 d = dist[i];
    float2 w;
    w.x = m.x ? __expf(-4.0f * d.x * d.x) : -1.0f;
    w.y = m.y ? __expf(-4.0f * d.y * d.y) : -1.0f;
    wm[i] = w;
}

// ============================================================================
// fp16 2-mma GEMM via mma.sync.m16n8k16, 3-stage pipeline, 128x256 CTA tile.
//   C = sum_n (A_n_hi + A_n_lo) @ W_n_hi + sum_n bias_n[N]
// 8 warps: 2m x 4n, each 64m x 64n. outmode 0: fp32; 1: f16 hi/lo; 2: f16.
// ============================================================================
#define ASTR 72
#define WSTR 264
#define GBN  256
#define BKC  64
#define A_BYTES (128 * ASTR * 2)                   // 18432
#define W_BYTES (64 * WSTR * 2)                    // 33792
#define BUF_BYTES (2 * A_BYTES + W_BYTES)          // 70656
#define SMB_BUF 1024
#define GEMM_SMEM (SMB_BUF + 3 * BUF_BYTES)        // 212992

__device__ __forceinline__ void load_chunk(
    uint32_t sbuf, const f16* __restrict__ Ah, const f16* __restrict__ Al,
    const f16* __restrict__ Wh, int bm, int bn, int k0, int tid)
{
    #pragma unroll
    for (int v = 0; v < 4; v++) {
        int idx = tid + v * 256;
        int r = idx >> 3, c = idx & 7;
        size_t go = (size_t)(bm + r) * C_ + k0 + c * 8;
        uint32_t so = sbuf + r * (ASTR * 2) + c * 16;
        CP_ASYNC16(so, Ah + go);
        CP_ASYNC16(so + A_BYTES, Al + go);
    }
    #pragma unroll
    for (int v = 0; v < 8; v++) {
        int idx = tid + v * 256;
        int r = idx >> 5, c = idx & 31;
        size_t go = (size_t)(k0 + r) * C_ + bn + c * 8;
        uint32_t so = sbuf + 2 * A_BYTES + r * (WSTR * 2) + c * 16;
        CP_ASYNC16(so, Wh + go);
    }
}

__device__ __forceinline__ void compute_chunk(
    uint32_t sbuf, int wm_, int wn, int lane, float acc[4][8][4])
{
    const uint32_t smAh = sbuf;
    const uint32_t smAl = sbuf + A_BYTES;
    const uint32_t smWh = sbuf + 2 * A_BYTES;
    const int m0 = wm_ * 64, n0 = wn * 64;
    const int ar = lane & 15;
    const int ac = (lane >> 4) << 3;

    #pragma unroll
    for (int ks = 0; ks < 4; ks++) {
        const int kk = ks * 16;
        uint32_t ah[4][4], al[4][4], bh[4][4];
        #pragma unroll
        for (int mi = 0; mi < 4; mi++) {
            uint32_t off = ((m0 + mi * 16 + ar) * ASTR + kk + ac) * 2;
            LDSM_X4(ah[mi][0], ah[mi][1], ah[mi][2], ah[mi][3], smAh + off);
            LDSM_X4(al[mi][0], al[mi][1], al[mi][2], al[mi][3], smAl + off);
        }
        #pragma unroll
        for (int nj = 0; nj < 4; nj++) {
            uint32_t off = ((kk + ar) * WSTR + n0 + nj * 16 +
                            ((lane >> 4) & 1) * 8) * 2;
            LDSM_X4T(bh[nj][0], bh[nj][1], bh[nj][2], bh[nj][3], smWh + off);
        }
        #pragma unroll
        for (int mi = 0; mi < 4; mi++)
            #pragma unroll
            for (int nj = 0; nj < 4; nj++) {
                MMA16816(acc[mi][nj * 2],     ah[mi], bh[nj][0], bh[nj][1]);
                MMA16816(acc[mi][nj * 2],     al[mi], bh[nj][0], bh[nj][1]);
                MMA16816(acc[mi][nj * 2 + 1], ah[mi], bh[nj][2], bh[nj][3]);
                MMA16816(acc[mi][nj * 2 + 1], al[mi], bh[nj][2], bh[nj][3]);
            }
    }
}

__global__ __launch_bounds__(256) void gemm_mma_kernel(
    const f16* __restrict__ Ah, const f16* __restrict__ Al,
    const f16* __restrict__ Wh,
    const float* __restrict__ bias, float* __restrict__ C,
    f16* __restrict__ Chi, f16* __restrict__ Clo,
    int nmat, size_t strideA, size_t strideW, int outmode)
{
    extern __shared__ char smc[];
    const uint32_t smb = smem_u32(smc);
    float* s_bias = (float*)smc;

    const int tid = threadIdx.x;
    const int lane = tid & 31;
    const int wid = tid >> 5;
    const int wm_ = wid & 1;
    const int wn = wid >> 1;
    const int bm = blockIdx.y * 128;
    const int bn = blockIdx.x * GBN;

    {
        float bs = 0.f;
        for (int n = 0; n < nmat; n++) bs += bias[(size_t)n * C_ + bn + tid];
        s_bias[tid] = bs;
    }

    float acc[4][8][4];
    #pragma unroll
    for (int mi = 0; mi < 4; mi++)
        #pragma unroll
        for (int ni = 0; ni < 8; ni++)
            #pragma unroll
            for (int r = 0; r < 4; r++) acc[mi][ni][r] = 0.f;

    const int NC = nmat * (C_ / BKC);

    // prologue: chunks 0, 1
    load_chunk(smb + SMB_BUF, Ah, Al, Wh, bm, bn, 0, tid);
    CP_COMMIT();
    load_chunk(smb + SMB_BUF + BUF_BYTES, Ah, Al, Wh, bm, bn, BKC, tid);
    CP_COMMIT();

    for (int c = 0; c < NC; c++) {
        if (c + 1 < NC) { CP_WAIT(1); } else { CP_WAIT(0); }
        __syncthreads();
        if (c + 2 < NC) {
            int cc = c + 2;
            int nm = cc >> 4;
            int k0 = (cc & 15) * BKC;
            load_chunk(smb + SMB_BUF + (cc % 3) * BUF_BYTES,
                       Ah + (size_t)nm * strideA, Al + (size_t)nm * strideA,
                       Wh + (size_t)nm * strideW, bm, bn, k0, tid);
            CP_COMMIT();
        }
        compute_chunk(smb + SMB_BUF + (c % 3) * BUF_BYTES, wm_, wn, lane, acc);
    }

    const int r0 = bm + wm_ * 64 + (lane >> 2);
    const int c0rel = wn * 64 + 2 * (lane & 3);
    #pragma unroll
    for (int mi = 0; mi < 4; mi++) {
        #pragma unroll
        for (int ni = 0; ni < 8; ni++) {
            int crel = c0rel + ni * 8;
            float b0 = s_bias[crel], b1 = s_bias[crel + 1];
            int row = r0 + mi * 16;
            float a0 = acc[mi][ni][0] + b0, a1 = acc[mi][ni][1] + b1;
            float a2 = acc[mi][ni][2] + b0, a3 = acc[mi][ni][3] + b1;
            if (outmode == 0) {
                *(float2*)&C[(size_t)row * C_ + bn + crel] = make_float2(a0, a1);
                *(float2*)&C[(size_t)(row + 8) * C_ + bn + crel] = make_float2(a2, a3);
            } else if (outmode == 1) {
                uint32_t h0, l0, h1, l1;
                split2h(a0, a1, h0, l0);
                split2h(a2, a3, h1, l1);
                *(uint32_t*)&Chi[(size_t)row * C_ + bn + crel] = h0;
                *(uint32_t*)&Clo[(size_t)row * C_ + bn + crel] = l0;
                *(uint32_t*)&Chi[(size_t)(row + 8) * C_ + bn + crel] = h1;
                *(uint32_t*)&Clo[(size_t)(row + 8) * C_ + bn + crel] = l1;
            } else {
                *(uint32_t*)&Chi[(size_t)row * C_ + bn + crel] = pack_h2(a0, a1);
                *(uint32_t*)&Chi[(size_t)(row + 8) * C_ + bn + crel] = pack_h2(a2, a3);
            }
        }
    }
}

// ============================================================================
// Flash attention: fp16 2-mma, register softmax, hoisted Q fragments,
// 3-stage KV pipeline with 128-row chunks processed as two 64-halves.
// CTA: 128 q-rows, 8 warps (16 q-rows each).
// ============================================================================
#define FQ 128
#define FS 64
#define FSTR 72
#define OFF_QH 0
#define OFF_QL 18432
#define OFF_BUF 36864
#define KV_HALF_BYTES 18432                        // K 9216 + V 9216 per 64 rows
#define KV_BUF_BYTES (2 * KV_HALF_BYTES)           // 36864 per 128-row chunk
#define FLASH_SMEM (OFF_BUF + 3 * KV_BUF_BYTES)    // 147456

__device__ __forceinline__ void flash_load_kv128(
    uint32_t bb, const f16* __restrict__ Kh, const f16* __restrict__ Vh,
    int b, int h, int s0, int tid)
{
    // 128 kv rows: two 64-row halves, each [K 9216 | V 9216]
    #pragma unroll
    for (int v = 0; v < 4; v++) {
        int idx = tid + v * 256;         // 0..1023
        int r = idx >> 3, c = idx & 7;   // r 0..127
        size_t go = (size_t)(b * T_ + s0 + r) * C_ + h * HD_ + c * 8;
        uint32_t so = bb + (r >> 6) * KV_HALF_BYTES + (r & 63) * (FSTR * 2) + c * 16;
        CP_ASYNC16(so,        Kh + go);
        CP_ASYNC16(so + 9216, Vh + go);
    }
}

__global__ __launch_bounds__(256) void flash_mma_kernel(
    const f16* __restrict__ Qh, const f16* __restrict__ Ql,
    const f16* __restrict__ Kh, const f16* __restrict__ Vh,
    const float* __restrict__ wm, f16* __restrict__ Ohi,
    f16* __restrict__ Olo)
{
    extern __shared__ char smc[];
    const uint32_t smb = smem_u32(smc);

    const int bh  = blockIdx.x;
    const int b   = bh >> 4;
    const int h   = bh & 15;
    const int t10 = blockIdx.y * FQ;
    const int tid = threadIdx.x;
    const int lane = tid & 31;
    const int wid = tid >> 5;
    const int m0 = wid * 16;
    const int g  = lane >> 2;
    const int c2 = (lane & 3) * 2;

    const int qr0 = t10 + m0 + g;
    const int qr1 = qr0 + 8;
    const float* wrow0 = &wm[(size_t)(b * T_ + qr0) * T_];
    const float* wrow1 = &wm[(size_t)(b * T_ + qr1) * T_];

    // ---- load Q tile (hi/lo) ----
    #pragma unroll
    for (int v = 0; v < 4; v++) {
        int idx = tid + v * 256;
        int r = idx >> 3, c = idx & 7;
        size_t go = (size_t)(b * T_ + t10 + r) * C_ + h * HD_ + c * 8;
        uint32_t so = smb + r * (FSTR * 2) + c * 16;
        CP_ASYNC16(so + OFF_QH, Qh + go);
        CP_ASYNC16(so + OFF_QL, Ql + go);
    }
    CP_COMMIT();
    // ---- kv chunks 0, 1 (128 rows each) ----
    flash_load_kv128(smb + OFF_BUF, Kh, Vh, b, h, 0, tid);
    CP_COMMIT();
    flash_load_kv128(smb + OFF_BUF + KV_BUF_BYTES, Kh, Vh, b, h, 128, tid);
    CP_COMMIT();

    // ---- hoist Q fragments to registers (loop-invariant) ----
    uint32_t qfh[4][4], qfl[4][4];
    CP_WAIT(2);                 // Q group done (kv0, kv1 still pending)
    __syncthreads();
    #pragma unroll
    for (int ks = 0; ks < 4; ks++) {
        uint32_t aoff = ((m0 + (lane & 15)) * FSTR + ks * 16 + ((lane >> 4) << 3)) * 2;
        LDSM_X4(qfh[ks][0], qfh[ks][1], qfh[ks][2], qfh[ks][3], smb + OFF_QH + aoff);
        LDSM_X4(qfl[ks][0], qfl[ks][1], qfl[ks][2], qfl[ks][3], smb + OFF_QL + aoff);
    }

    float mstat0 = -3.0e38f, mstat1 = -3.0e38f;
    float lstat0 = 0.f, lstat1 = 0.f;

    float oacc[8][4];
    #pragma unroll
    for (int ni = 0; ni < 8; ni++)
        #pragma unroll
        for (int r = 0; r < 4; r++) oacc[ni][r] = 0.f;

    const int NITER = T_ / 128;          // 16

    for (int it = 0; it < NITER; it++) {
        if (it + 1 < NITER) { CP_WAIT(1); } else { CP_WAIT(0); }
        __syncthreads();
        if (it + 2 < NITER) {
            flash_load_kv128(smb + OFF_BUF + ((it + 2) % 3) * KV_BUF_BYTES,
                             Kh, Vh, b, h, (it + 2) * 128, tid);
            CP_COMMIT();
        }

        #pragma unroll
        for (int h2 = 0; h2 < 2; h2++) {
            const int s0 = it * 128 + h2 * FS;
            const uint32_t bb = smb + OFF_BUF + (it % 3) * KV_BUF_BYTES +
                                h2 * KV_HALF_BYTES;
            const uint32_t smKh = bb;
            const uint32_t smVh = bb + 9216;

            // ---- S = (Qh + Ql) K^T ----
            float sacc[8][4];
            #pragma unroll
            for (int ni = 0; ni < 8; ni++)
                #pragma unroll
                for (int r = 0; r < 4; r++) sacc[ni][r] = 0.f;

            #pragma unroll
            for (int ks = 0; ks < 4; ks++) {
                const int k0 = ks * 16;
                #pragma unroll
                for (int nj = 0; nj < 4; nj++) {
                    uint32_t kh4[4];
                    uint32_t boff = ((nj * 16 + (lane & 7) + ((lane >> 4) << 3)) * FSTR +
                                     k0 + ((lane >> 3) & 1) * 8) * 2;
                    LDSM_X4(kh4[0], kh4[1], kh4[2], kh4[3], smKh + boff);
                    MMA16816(sacc[nj * 2],     qfh[ks], kh4[0], kh4[1]);
                    MMA16816(sacc[nj * 2],     qfl[ks], kh4[0], kh4[1]);
                    MMA16816(sacc[nj * 2 + 1], qfh[ks], kh4[2], kh4[3]);
                    MMA16816(sacc[nj * 2 + 1], qfl[ks], kh4[2], kh4[3]);
                }
            }

            // ---- wm load: scale + mask via sign ----
            float wreg[8][4];
            #pragma unroll
            for (int ni = 0; ni < 8; ni++) {
                int s = s0 + ni * 8 + c2;
                float2 w0 = *(const float2*)&wrow0[s];
                float2 w1 = *(const float2*)&wrow1[s];
                wreg[ni][0] = w0.x; wreg[ni][1] = w0.y;
                wreg[ni][2] = w1.x; wreg[ni][3] = w1.y;
                sacc[ni][0] = w0.x > 0.f ? sacc[ni][0] * 0.125f : NEG_;
                sacc[ni][1] = w0.y > 0.f ? sacc[ni][1] * 0.125f : NEG_;
                sacc[ni][2] = w1.x > 0.f ? sacc[ni][2] * 0.125f : NEG_;
                sacc[ni][3] = w1.y > 0.f ? sacc[ni][3] * 0.125f : NEG_;
            }

            // ---- row max ----
            float mx0 = -3.0e38f, mx1 = -3.0e38f;
            #pragma unroll
            for (int ni = 0; ni < 8; ni++) {
                mx0 = fmaxf(mx0, fmaxf(sacc[ni][0], sacc[ni][1]));
                mx1 = fmaxf(mx1, fmaxf(sacc[ni][2], sacc[ni][3]));
            }
            mx0 = fmaxf(mx0, __shfl_xor_sync(0xffffffff, mx0, 1));
            mx0 = fmaxf(mx0, __shfl_xor_sync(0xffffffff, mx0, 2));
            mx1 = fmaxf(mx1, __shfl_xor_sync(0xffffffff, mx1, 1));
            mx1 = fmaxf(mx1, __shfl_xor_sync(0xffffffff, mx1, 2));

            float mnew0 = fmaxf(mstat0, mx0);
            float mnew1 = fmaxf(mstat1, mx1);
            float fr0 = __expf(mstat0 - mnew0);
            float fr1 = __expf(mstat1 - mnew1);
            mstat0 = mnew0; mstat1 = mnew1;

            // ---- exp + row sum ----
            float sum0 = 0.f, sum1 = 0.f;
            #pragma unroll
            for (int ni = 0; ni < 8; ni++) {
                sacc[ni][0] = __expf(sacc[ni][0] - mnew0);
                sacc[ni][1] = __expf(sacc[ni][1] - mnew0);
                sacc[ni][2] = __expf(sacc[ni][2] - mnew1);
                sacc[ni][3] = __expf(sacc[ni][3] - mnew1);
                sum0 += sacc[ni][0] + sacc[ni][1];
                sum1 += sacc[ni][2] + sacc[ni][3];
            }
            sum0 += __shfl_xor_sync(0xffffffff, sum0, 1);
            sum0 += __shfl_xor_sync(0xffffffff, sum0, 2);
            sum1 += __shfl_xor_sync(0xffffffff, sum1, 1);
            sum1 += __shfl_xor_sync(0xffffffff, sum1, 2);
            lstat0 = lstat0 * fr0 + sum0;
            lstat1 = lstat1 * fr1 + sum1;

            // ---- numerator modulation + pack P fragments (hi/lo, exact) ----
            uint32_t aH[4][4], aL[4][4];
            #pragma unroll
            for (int j = 0; j < 4; j++) {
                #pragma unroll
                for (int half = 0; half < 2; half++) {
                    int ni = 2 * j + half;
                    float p00 = sacc[ni][0] * wreg[ni][0];
                    float p01 = sacc[ni][1] * wreg[ni][1];
                    float p10 = sacc[ni][2] * wreg[ni][2];
                    float p11 = sacc[ni][3] * wreg[ni][3];
                    split2h(p00, p01, aH[j][half * 2 + 0], aL[j][half * 2 + 0]);
                    split2h(p10, p11, aH[j][half * 2 + 1], aL[j][half * 2 + 1]);
                }
            }

            // ---- rescale O, then O += (Ph + Pl) @ V ----
            #pragma unroll
            for (int ni = 0; ni < 8; ni++) {
                oacc[ni][0] *= fr0; oacc[ni][1] *= fr0;
                oacc[ni][2] *= fr1; oacc[ni][3] *= fr1;
            }
            #pragma unroll
            for (int j = 0; j < 4; j++) {
                #pragma unroll
                for (int nj = 0; nj < 4; nj++) {
                    uint32_t vh4[4];
                    uint32_t boff = ((j * 16 + (lane & 15)) * FSTR +
                                     (nj * 2 + ((lane >> 4) & 1)) * 8) * 2;
                    LDSM_X4T(vh4[0], vh4[1], vh4[2], vh4[3], smVh + boff);
                    MMA16816(oacc[nj * 2],     aH[j], vh4[0], vh4[1]);
                    MMA16816(oacc[nj * 2],     aL[j], vh4[0], vh4[1]);
                    MMA16816(oacc[nj * 2 + 1], aH[j], vh4[2], vh4[3]);
                    MMA16816(oacc[nj * 2 + 1], aL[j], vh4[2], vh4[3]);
                }
            }
        }
    }

    // ---- epilogue: /l, write f16 hi/lo ----
    {
        float inv0 = 1.0f / lstat0;
        float inv1 = 1.0f / lstat1;
        size_t row0 = (size_t)(b * T_ + qr0) * C_ + h * HD_;
        size_t row1 = (size_t)(b * T_ + qr1) * C_ + h * HD_;
        #pragma unroll
        for (int ni = 0; ni < 8; ni++) {
            int c = ni * 8 + c2;
            uint32_t h0, l0, h1, l1;
            split2h(oacc[ni][0] * inv0, oacc[ni][1] * inv0, h0, l0);
            split2h(oacc[ni][2] * inv1, oacc[ni][3] * inv1, h1, l1);
            *(uint32_t*)&Ohi[row0 + c] = h0;
            *(uint32_t*)&Olo[row0 + c] = l0;
            *(uint32_t*)&Ohi[row1 + c] = h1;
            *(uint32_t*)&Olo[row1 + c] = l1;
        }
    }
}

// ============================================================================
// Launch
// ============================================================================
extern "C" void kernel_launch(void* const* d_in, const int* in_sizes, int n_in,
                              void* d_out, int out_size)
{
    const float* x_q  = (const float*)d_in[0];
    const float* x_r  = (const float*)d_in[1];
    const float* y    = (const float*)d_in[2];
    const int*   mask = (const int*)  d_in[3];
    const float* dist = (const float*)d_in[4];
    const float* Wq   = (const float*)d_in[5];
    const float* bq   = (const float*)d_in[6];
    const float* Wk   = (const float*)d_in[7];
    const float* bk   = (const float*)d_in[8];
    const float* Wv   = (const float*)d_in[9];
    const float* bv   = (const float*)d_in[10];
    const float* Wp   = (const float*)d_in[11];
    const float* bp   = (const float*)d_in[12];
    float* out = (float*)d_out;

    f16 *qh, *ql, *kh, *vh;
    f16 *xqh, *xql, *xrh, *xrl, *yh, *yl, *Oh, *Ol;
    f16 *wqh, *wkh, *wvh, *wph;
    float* wmp;
    cudaGetSymbolAddress((void**)&qh,  g_Qh);
    cudaGetSymbolAddress((void**)&ql,  g_Ql);
    cudaGetSymbolAddress((void**)&kh,  g_Kh);
    cudaGetSymbolAddress((void**)&vh,  g_Vh);
    cudaGetSymbolAddress((void**)&xqh, g_xqh);
    cudaGetSymbolAddress((void**)&xql, g_xql);
    cudaGetSymbolAddress((void**)&xrh, g_xrh);
    cudaGetSymbolAddress((void**)&xrl, g_xrl);
    cudaGetSymbolAddress((void**)&yh,  g_yh);
    cudaGetSymbolAddress((void**)&yl,  g_yl);
    cudaGetSymbolAddress((void**)&Oh,  g_Oh);
    cudaGetSymbolAddress((void**)&Ol,  g_Ol);
    cudaGetSymbolAddress((void**)&wqh, g_Wqh);
    cudaGetSymbolAddress((void**)&wkh, g_Wkh);
    cudaGetSymbolAddress((void**)&wvh, g_Wvh);
    cudaGetSymbolAddress((void**)&wph, g_Wph);
    cudaGetSymbolAddress((void**)&wmp, g_wm);

    cudaFuncSetAttribute(gemm_mma_kernel,
                         cudaFuncAttributeMaxDynamicSharedMemorySize, GEMM_SMEM);
    cudaFuncSetAttribute(flash_mma_kernel,
                         cudaFuncAttributeMaxDynamicSharedMemorySize, FLASH_SMEM);

    // ---- split activations (hi/lo), quantize weights (single), build wm ----
    const int MC4 = M_ * C_ / 4;
    const int CC4 = C_ * C_ / 4;
    split_kernel<<<MC4 / 256, 256>>>((const float4*)x_q, (uint2*)xqh, (uint2*)xql, MC4);
    split_kernel<<<MC4 / 256, 256>>>((const float4*)x_r, (uint2*)xrh, (uint2*)xrl, MC4);
    split_kernel<<<NI_ * MC4 / 256, 256>>>((const float4*)y, (uint2*)yh, (uint2*)yl, NI_ * MC4);
    quant_kernel<<<CC4 / 256, 256>>>((const float4*)Wq, (uint2*)wqh, CC4);
    quant_kernel<<<CC4 / 256, 256>>>((const float4*)Wk, (uint2*)wkh, CC4);
    quant_kernel<<<NI_ * CC4 / 256, 256>>>((const float4*)Wv, (uint2*)wvh, NI_ * CC4);
    quant_kernel<<<CC4 / 256, 256>>>((const float4*)Wp, (uint2*)wph, CC4);
    {
        const int n2 = B_ * T_ * T_ / 2;
        wm_kernel<<<(n2 + 255) / 256, 256>>>((const int2*)mask,
                                             (const float2*)dist,
                                             (float2*)wmp, n2);
    }

    dim3 gblk(256);
    dim3 ggrd(C_ / GBN, M_ / 128);       // (4, 32) = 128 CTAs

    // projections: Q -> hi/lo, K -> single, V -> single
    gemm_mma_kernel<<<ggrd, gblk, GEMM_SMEM>>>(xqh, xql, wqh, bq,
                                               nullptr, qh, ql, 1, 0, 0, 1);
    gemm_mma_kernel<<<ggrd, gblk, GEMM_SMEM>>>(xrh, xrl, wkh, bk,
                                               nullptr, kh, nullptr, 1, 0, 0, 2);
    gemm_mma_kernel<<<ggrd, gblk, GEMM_SMEM>>>(yh, yl, wvh, bv,
                                               nullptr, vh, nullptr, NI_,
                                               (size_t)M_ * C_, (size_t)C_ * C_, 2);

    dim3 fgrd(B_ * H_, T_ / FQ);         // (32, 16)
    flash_mma_kernel<<<fgrd, 256, FLASH_SMEM>>>(qh, ql, kh, vh, wmp, Oh, Ol);

    // out projection -> fp32
    gemm_mma_kernel<<<ggrd, gblk, GEMM_SMEM>>>(Oh, Ol, wph, bp,
                                               out, nullptr, nullptr, 1, 0, 0, 0);
}

// round 13
// speedup vs baseline: 1.0585x; 1.0585x over previous
#include <cuda_runtime.h>
#include <cuda_fp16.h>
#include <cstdint>

// Problem shape (fixed by dataset)
#define B_  2
#define T_  2048
#define C_  1024
#define H_  16
#define HD_ 64
#define NI_ 3
#define M_  (B_ * T_)
#define NEG_ (-1e9f)

typedef __half f16;

// -------- scratch (device globals; no allocation allowed) --------
__device__ f16 g_Qh[(size_t)M_ * C_],       g_Ql[(size_t)M_ * C_];
__device__ f16 g_Kh[(size_t)M_ * C_];
__device__ f16 g_Vh[(size_t)M_ * C_];
__device__ f16 g_xqh[(size_t)M_ * C_],      g_xql[(size_t)M_ * C_];
__device__ f16 g_xrh[(size_t)M_ * C_],      g_xrl[(size_t)M_ * C_];
__device__ f16 g_yh [(size_t)NI_ * M_ * C_], g_yl [(size_t)NI_ * M_ * C_];
__device__ f16 g_Oh [(size_t)M_ * C_],      g_Ol [(size_t)M_ * C_];
__device__ f16 g_Wqh[(size_t)C_ * C_];
__device__ f16 g_Wkh[(size_t)C_ * C_];
__device__ f16 g_Wvh[(size_t)NI_ * C_ * C_];
__device__ f16 g_Wph[(size_t)C_ * C_];
__device__ float g_wm[(size_t)B_ * T_ * T_];  // mask? exp(-4d^2) : -1

// ============================================================================
// helpers
// ============================================================================
__device__ __forceinline__ uint32_t smem_u32(const void* p) {
    uint32_t a;
    asm("{ .reg .u64 t; cvta.to.shared.u64 t, %1; cvt.u32.u64 %0, t; }"
        : "=r"(a) : "l"(p));
    return a;
}
__device__ __forceinline__ uint32_t pack_h2(float a, float b) {
    f16 h0 = __float2half_rn(a);
    f16 h1 = __float2half_rn(b);
    return ((uint32_t)__half_as_ushort(h1) << 16) | __half_as_ushort(h0);
}
__device__ __forceinline__ void split2h(float a, float b, uint32_t& hi, uint32_t& lo) {
    f16 h0 = __float2half_rn(a);
    f16 h1 = __float2half_rn(b);
    hi = ((uint32_t)__half_as_ushort(h1) << 16) | __half_as_ushort(h0);
    lo = pack_h2(a - __half2float(h0), b - __half2float(h1));
}

#define CP_ASYNC16(dst, src) \
    asm volatile("cp.async.cg.shared.global [%0], [%1], 16;" :: "r"(dst), "l"(src))
#define CP_COMMIT() asm volatile("cp.async.commit_group;" ::: "memory")
#define CP_WAIT(n)  asm volatile("cp.async.wait_group %0;" :: "n"(n) : "memory")

#define LDSM_X4(r0, r1, r2, r3, addr) \
    asm volatile("ldmatrix.sync.aligned.m8n8.x4.shared.b16 {%0,%1,%2,%3}, [%4];" \
                 : "=r"(r0), "=r"(r1), "=r"(r2), "=r"(r3) : "r"(addr))
#define LDSM_X4T(r0, r1, r2, r3, addr) \
    asm volatile("ldmatrix.sync.aligned.m8n8.x4.trans.shared.b16 {%0,%1,%2,%3}, [%4];" \
                 : "=r"(r0), "=r"(r1), "=r"(r2), "=r"(r3) : "r"(addr))

#define MMA16816(d, a, b0, b1) \
    asm volatile("mma.sync.aligned.m16n8k16.row.col.f32.f16.f16.f32 " \
                 "{%0,%1,%2,%3}, {%4,%5,%6,%7}, {%8,%9}, {%0,%1,%2,%3};" \
                 : "+f"((d)[0]), "+f"((d)[1]), "+f"((d)[2]), "+f"((d)[3]) \
                 : "r"((a)[0]), "r"((a)[1]), "r"((a)[2]), "r"((a)[3]), \
                   "r"(b0), "r"(b1))

// ============================================================================
// split kernel: fp32 -> f16 hi + f16 lo (residual)
// ============================================================================
__global__ __launch_bounds__(256) void split_kernel(
    const float4* __restrict__ in, uint2* __restrict__ hi,
    uint2* __restrict__ lo, int n4)
{
    int i = blockIdx.x * 256 + threadIdx.x;
    if (i >= n4) return;
    float4 f = in[i];
    uint32_t h0, l0, h1, l1;
    split2h(f.x, f.y, h0, l0);
    split2h(f.z, f.w, h1, l1);
    hi[i] = make_uint2(h0, h1);
    lo[i] = make_uint2(l0, l1);
}

// quant kernel: fp32 -> single f16 (weights)
__global__ __launch_bounds__(256) void quant_kernel(
    const float4* __restrict__ in, uint2* __restrict__ hi, int n4)
{
    int i = blockIdx.x * 256 + threadIdx.x;
    if (i >= n4) return;
    float4 f = in[i];
    hi[i] = make_uint2(pack_h2(f.x, f.y), pack_h2(f.z, f.w));
}

// ============================================================================
// wm kernel: wm = mask ? exp(-4 d^2) : -1
// ============================================================================
__global__ __launch_bounds__(256) void wm_kernel(
    const int2* __restrict__ mask, const float2* __restrict__ dist,
    float2* __restrict__ wm, int n2)
{
    int i = blockIdx.x * 256 + threadIdx.x;
    if (i >= n2) return;
    int2 m = mask[i];
    float2 d = dist[i];
    float2 w;
    w.x = m.x ? __expf(-4.0f * d.x * d.x) : -1.0f;
    w.y = m.y ? __expf(-4.0f * d.y * d.y) : -1.0f;
    wm[i] = w;
}

// ============================================================================
// fp16 2-mma GEMM via mma.sync.m16n8k16, 2-stage pipeline, 2 CTAs/SM.
//   C = sum_n (A_n_hi + A_n_lo) @ W_n_hi + sum_n bias_n[N]
// 128x128 CTA tile, 8 warps (2m x 4n).
// outmode 0: fp32 to C.  1: f16 hi/lo to Chi/Clo.  2: single f16 to Chi.
// ============================================================================
#define ASTR 72
#define WSTR 136
#define BKC  64
#define A_BYTES (128 * ASTR * 2)                   // 18432
#define W_BYTES (64 * WSTR * 2)                    // 17408
#define BUF_BYTES (2 * A_BYTES + W_BYTES)          // 54272
#define SMB_BUF 1024
#define GEMM_SMEM (SMB_BUF + 2 * BUF_BYTES)        // 109568 -> 2 CTAs/SM

__device__ __forceinline__ void load_chunk(
    uint32_t sbuf, const f16* __restrict__ Ah, const f16* __restrict__ Al,
    const f16* __restrict__ Wh, int bm, int bn, int k0, int tid)
{
    #pragma unroll
    for (int v = 0; v < 4; v++) {
        int idx = tid + v * 256;
        int r = idx >> 3, c = idx & 7;
        size_t go = (size_t)(bm + r) * C_ + k0 + c * 8;
        uint32_t so = sbuf + r * (ASTR * 2) + c * 16;
        CP_ASYNC16(so, Ah + go);
        CP_ASYNC16(so + A_BYTES, Al + go);
    }
    #pragma unroll
    for (int v = 0; v < 4; v++) {
        int idx = tid + v * 256;
        int r = idx >> 4, c = idx & 15;
        size_t go = (size_t)(k0 + r) * C_ + bn + c * 8;
        uint32_t so = sbuf + 2 * A_BYTES + r * (WSTR * 2) + c * 16;
        CP_ASYNC16(so, Wh + go);
    }
}

__device__ __forceinline__ void compute_chunk(
    uint32_t sbuf, int wm_, int wn, int lane, float acc[4][4][4])
{
    const uint32_t smAh = sbuf;
    const uint32_t smAl = sbuf + A_BYTES;
    const uint32_t smWh = sbuf + 2 * A_BYTES;
    const int m0 = wm_ * 64, n0 = wn * 32;
    const int ar = lane & 15;
    const int ac = (lane >> 4) << 3;

    #pragma unroll
    for (int ks = 0; ks < 4; ks++) {
        const int kk = ks * 16;
        uint32_t ah[4][4], al[4][4], bh[2][4];
        #pragma unroll
        for (int mi = 0; mi < 4; mi++) {
            uint32_t off = ((m0 + mi * 16 + ar) * ASTR + kk + ac) * 2;
            LDSM_X4(ah[mi][0], ah[mi][1], ah[mi][2], ah[mi][3], smAh + off);
            LDSM_X4(al[mi][0], al[mi][1], al[mi][2], al[mi][3], smAl + off);
        }
        #pragma unroll
        for (int nj = 0; nj < 2; nj++) {
            uint32_t off = ((kk + ar) * WSTR + n0 + nj * 16 +
                            ((lane >> 4) & 1) * 8) * 2;
            LDSM_X4T(bh[nj][0], bh[nj][1], bh[nj][2], bh[nj][3], smWh + off);
        }
        #pragma unroll
        for (int mi = 0; mi < 4; mi++)
            #pragma unroll
            for (int nj = 0; nj < 2; nj++) {
                MMA16816(acc[mi][nj * 2],     ah[mi], bh[nj][0], bh[nj][1]);
                MMA16816(acc[mi][nj * 2],     al[mi], bh[nj][0], bh[nj][1]);
                MMA16816(acc[mi][nj * 2 + 1], ah[mi], bh[nj][2], bh[nj][3]);
                MMA16816(acc[mi][nj * 2 + 1], al[mi], bh[nj][2], bh[nj][3]);
            }
    }
}

__global__ __launch_bounds__(256, 2) void gemm_mma_kernel(
    const f16* __restrict__ Ah, const f16* __restrict__ Al,
    const f16* __restrict__ Wh,
    const float* __restrict__ bias, float* __restrict__ C,
    f16* __restrict__ Chi, f16* __restrict__ Clo,
    int nmat, size_t strideA, size_t strideW, int outmode)
{
    extern __shared__ char smc[];
    const uint32_t smb = smem_u32(smc);
    float* s_bias = (float*)smc;

    const int tid = threadIdx.x;
    const int lane = tid & 31;
    const int wid = tid >> 5;
    const int wm_ = wid & 1;
    const int wn = wid >> 1;
    const int bm = blockIdx.y * 128;
    const int bn = blockIdx.x * 128;

    if (tid < 128) {
        float bs = 0.f;
        for (int n = 0; n < nmat; n++) bs += bias[(size_t)n * C_ + bn + tid];
        s_bias[tid] = bs;
    }

    float acc[4][4][4];
    #pragma unroll
    for (int mi = 0; mi < 4; mi++)
        #pragma unroll
        for (int ni = 0; ni < 4; ni++)
            #pragma unroll
            for (int r = 0; r < 4; r++) acc[mi][ni][r] = 0.f;

    const int NC = nmat * (C_ / BKC);

    // prologue: chunk 0
    load_chunk(smb + SMB_BUF, Ah, Al, Wh, bm, bn, 0, tid);
    CP_COMMIT();

    for (int c = 0; c < NC; c++) {
        if (c + 1 < NC) {
            int cc = c + 1;
            int nm = cc >> 4;
            int k0 = (cc & 15) * BKC;
            load_chunk(smb + SMB_BUF + (cc & 1) * BUF_BYTES,
                       Ah + (size_t)nm * strideA, Al + (size_t)nm * strideA,
                       Wh + (size_t)nm * strideW, bm, bn, k0, tid);
            CP_COMMIT();
            CP_WAIT(1);
        } else {
            CP_WAIT(0);
        }
        __syncthreads();
        compute_chunk(smb + SMB_BUF + (c & 1) * BUF_BYTES, wm_, wn, lane, acc);
        __syncthreads();
    }

    const int r0 = bm + wm_ * 64 + (lane >> 2);
    const int c0rel = wn * 32 + 2 * (lane & 3);
    #pragma unroll
    for (int mi = 0; mi < 4; mi++) {
        #pragma unroll
        for (int ni = 0; ni < 4; ni++) {
            int crel = c0rel + ni * 8;
            float b0 = s_bias[crel], b1 = s_bias[crel + 1];
            int row = r0 + mi * 16;
            float a0 = acc[mi][ni][0] + b0, a1 = acc[mi][ni][1] + b1;
            float a2 = acc[mi][ni][2] + b0, a3 = acc[mi][ni][3] + b1;
            if (outmode == 0) {
                *(float2*)&C[(size_t)row * C_ + bn + crel] = make_float2(a0, a1);
                *(float2*)&C[(size_t)(row + 8) * C_ + bn + crel] = make_float2(a2, a3);
            } else if (outmode == 1) {
                uint32_t h0, l0, h1, l1;
                split2h(a0, a1, h0, l0);
                split2h(a2, a3, h1, l1);
                *(uint32_t*)&Chi[(size_t)row * C_ + bn + crel] = h0;
                *(uint32_t*)&Clo[(size_t)row * C_ + bn + crel] = l0;
                *(uint32_t*)&Chi[(size_t)(row + 8) * C_ + bn + crel] = h1;
                *(uint32_t*)&Clo[(size_t)(row + 8) * C_ + bn + crel] = l1;
            } else {
                *(uint32_t*)&Chi[(size_t)row * C_ + bn + crel] = pack_h2(a0, a1);
                *(uint32_t*)&Chi[(size_t)(row + 8) * C_ + bn + crel] = pack_h2(a2, a3);
            }
        }
    }
}

// ============================================================================
// Flash attention: fp16 2-mma, register softmax, precomputed wm, 3-stage KV,
// 2 CTAs/SM. Q and P are the exact (hi/lo) side; K and V single-f16.
// CTA: 128 q-rows, kv chunks of 64, 8 warps (16 q-rows each).
// ============================================================================
#define FQ 128
#define FS 64
#define FSTR 72
#define OFF_QH 0
#define OFF_QL 18432
#define OFF_BUF 36864
#define KV_BUF_BYTES 18432                         // K 9216 + V 9216
#define FLASH_SMEM (OFF_BUF + 3 * KV_BUF_BYTES)    // 92160 -> 2 CTAs/SM

__device__ __forceinline__ void flash_load_kv(
    uint32_t bb, const f16* __restrict__ Kh, const f16* __restrict__ Vh,
    int b, int h, int s0, int tid)
{
    #pragma unroll
    for (int v = 0; v < 2; v++) {
        int idx = tid + v * 256;
        int r = idx >> 3, c = idx & 7;
        size_t go = (size_t)(b * T_ + s0 + r) * C_ + h * HD_ + c * 8;
        uint32_t so = bb + r * (FSTR * 2) + c * 16;
        CP_ASYNC16(so,        Kh + go);
        CP_ASYNC16(so + 9216, Vh + go);
    }
}

__global__ __launch_bounds__(256, 2) void flash_mma_kernel(
    const f16* __restrict__ Qh, const f16* __restrict__ Ql,
    const f16* __restrict__ Kh, const f16* __restrict__ Vh,
    const float* __restrict__ wm, f16* __restrict__ Ohi,
    f16* __restrict__ Olo)
{
    extern __shared__ char smc[];
    const uint32_t smb = smem_u32(smc);

    const int bh  = blockIdx.x;
    const int b   = bh >> 4;
    const int h   = bh & 15;
    const int t10 = blockIdx.y * FQ;
    const int tid = threadIdx.x;
    const int lane = tid & 31;
    const int wid = tid >> 5;
    const int m0 = wid * 16;
    const int g  = lane >> 2;
    const int c2 = (lane & 3) * 2;

    const int qr0 = t10 + m0 + g;
    const int qr1 = qr0 + 8;
    const float* wrow0 = &wm[(size_t)(b * T_ + qr0) * T_];
    const float* wrow1 = &wm[(size_t)(b * T_ + qr1) * T_];

    // ---- load Q tile (hi/lo) ----
    #pragma unroll
    for (int v = 0; v < 4; v++) {
        int idx = tid + v * 256;
        int r = idx >> 3, c = idx & 7;
        size_t go = (size_t)(b * T_ + t10 + r) * C_ + h * HD_ + c * 8;
        uint32_t so = smb + r * (FSTR * 2) + c * 16;
        CP_ASYNC16(so + OFF_QH, Qh + go);
        CP_ASYNC16(so + OFF_QL, Ql + go);
    }
    CP_COMMIT();
    // ---- kv chunks 0, 1 ----
    flash_load_kv(smb + OFF_BUF, Kh, Vh, b, h, 0, tid);
    CP_COMMIT();
    flash_load_kv(smb + OFF_BUF + KV_BUF_BYTES, Kh, Vh, b, h, FS, tid);
    CP_COMMIT();

    float mstat0 = -3.0e38f, mstat1 = -3.0e38f;
    float lstat0 = 0.f, lstat1 = 0.f;

    float oacc[8][4];
    #pragma unroll
    for (int ni = 0; ni < 8; ni++)
        #pragma unroll
        for (int r = 0; r < 4; r++) oacc[ni][r] = 0.f;

    const int NITER = T_ / FS;           // 32

    for (int it = 0; it < NITER; it++) {
        if (it + 1 < NITER) { CP_WAIT(1); } else { CP_WAIT(0); }
        __syncthreads();
        if (it + 2 < NITER) {
            flash_load_kv(smb + OFF_BUF + ((it + 2) % 3) * KV_BUF_BYTES,
                          Kh, Vh, b, h, (it + 2) * FS, tid);
            CP_COMMIT();
        }

        const int s0 = it * FS;
        const uint32_t bb = smb + OFF_BUF + (it % 3) * KV_BUF_BYTES;
        const uint32_t smKh = bb;
        const uint32_t smVh = bb + 9216;

        // ---- S = (Qh + Ql) K^T ----
        float sacc[8][4];
        #pragma unroll
        for (int ni = 0; ni < 8; ni++)
            #pragma unroll
            for (int r = 0; r < 4; r++) sacc[ni][r] = 0.f;

        #pragma unroll
        for (int ks = 0; ks < 4; ks++) {
            const int k0 = ks * 16;
            uint32_t qh[4], ql[4];
            uint32_t aoff = ((m0 + (lane & 15)) * FSTR + k0 + ((lane >> 4) << 3)) * 2;
            LDSM_X4(qh[0], qh[1], qh[2], qh[3], smb + OFF_QH + aoff);
            LDSM_X4(ql[0], ql[1], ql[2], ql[3], smb + OFF_QL + aoff);
            #pragma unroll
            for (int nj = 0; nj < 4; nj++) {
                uint32_t kh4[4];
                uint32_t boff = ((nj * 16 + (lane & 7) + ((lane >> 4) << 3)) * FSTR +
                                 k0 + ((lane >> 3) & 1) * 8) * 2;
                LDSM_X4(kh4[0], kh4[1], kh4[2], kh4[3], smKh + boff);
                MMA16816(sacc[nj * 2],     qh, kh4[0], kh4[1]);
                MMA16816(sacc[nj * 2],     ql, kh4[0], kh4[1]);
                MMA16816(sacc[nj * 2 + 1], qh, kh4[2], kh4[3]);
                MMA16816(sacc[nj * 2 + 1], ql, kh4[2], kh4[3]);
            }
        }

        // ---- wm load: scale + mask via sign ----
        float wreg[8][4];
        #pragma unroll
        for (int ni = 0; ni < 8; ni++) {
            int s = s0 + ni * 8 + c2;
            float2 w0 = *(const float2*)&wrow0[s];
            float2 w1 = *(const float2*)&wrow1[s];
            wreg[ni][0] = w0.x; wreg[ni][1] = w0.y;
            wreg[ni][2] = w1.x; wreg[ni][3] = w1.y;
            sacc[ni][0] = w0.x > 0.f ? sacc[ni][0] * 0.125f : NEG_;
            sacc[ni][1] = w0.y > 0.f ? sacc[ni][1] * 0.125f : NEG_;
            sacc[ni][2] = w1.x > 0.f ? sacc[ni][2] * 0.125f : NEG_;
            sacc[ni][3] = w1.y > 0.f ? sacc[ni][3] * 0.125f : NEG_;
        }

        // ---- row max ----
        float mx0 = -3.0e38f, mx1 = -3.0e38f;
        #pragma unroll
        for (int ni = 0; ni < 8; ni++) {
            mx0 = fmaxf(mx0, fmaxf(sacc[ni][0], sacc[ni][1]));
            mx1 = fmaxf(mx1, fmaxf(sacc[ni][2], sacc[ni][3]));
        }
        mx0 = fmaxf(mx0, __shfl_xor_sync(0xffffffff, mx0, 1));
        mx0 = fmaxf(mx0, __shfl_xor_sync(0xffffffff, mx0, 2));
        mx1 = fmaxf(mx1, __shfl_xor_sync(0xffffffff, mx1, 1));
        mx1 = fmaxf(mx1, __shfl_xor_sync(0xffffffff, mx1, 2));

        float mnew0 = fmaxf(mstat0, mx0);
        float mnew1 = fmaxf(mstat1, mx1);
        float fr0 = __expf(mstat0 - mnew0);
        float fr1 = __expf(mstat1 - mnew1);
        mstat0 = mnew0; mstat1 = mnew1;

        // ---- exp + row sum ----
        float sum0 = 0.f, sum1 = 0.f;
        #pragma unroll
        for (int ni = 0; ni < 8; ni++) {
            sacc[ni][0] = __expf(sacc[ni][0] - mnew0);
            sacc[ni][1] = __expf(sacc[ni][1] - mnew0);
            sacc[ni][2] = __expf(sacc[ni][2] - mnew1);
            sacc[ni][3] = __expf(sacc[ni][3] - mnew1);
            sum0 += sacc[ni][0] + sacc[ni][1];
            sum1 += sacc[ni][2] + sacc[ni][3];
        }
        sum0 += __shfl_xor_sync(0xffffffff, sum0, 1);
        sum0 += __shfl_xor_sync(0xffffffff, sum0, 2);
        sum1 += __shfl_xor_sync(0xffffffff, sum1, 1);
        sum1 += __shfl_xor_sync(0xffffffff, sum1, 2);
        lstat0 = lstat0 * fr0 + sum0;
        lstat1 = lstat1 * fr1 + sum1;

        // ---- numerator modulation + pack P fragments (hi/lo, exact) ----
        uint32_t aH[4][4], aL[4][4];
        #pragma unroll
        for (int j = 0; j < 4; j++) {
            #pragma unroll
            for (int half = 0; half < 2; half++) {
                int ni = 2 * j + half;
                float p00 = sacc[ni][0] * wreg[ni][0];
                float p01 = sacc[ni][1] * wreg[ni][1];
                float p10 = sacc[ni][2] * wreg[ni][2];
                float p11 = sacc[ni][3] * wreg[ni][3];
                split2h(p00, p01, aH[j][half * 2 + 0], aL[j][half * 2 + 0]);
                split2h(p10, p11, aH[j][half * 2 + 1], aL[j][half * 2 + 1]);
            }
        }

        // ---- rescale O, then O += (Ph + Pl) @ V ----
        #pragma unroll
        for (int ni = 0; ni < 8; ni++) {
            oacc[ni][0] *= fr0; oacc[ni][1] *= fr0;
            oacc[ni][2] *= fr1; oacc[ni][3] *= fr1;
        }
        #pragma unroll
        for (int j = 0; j < 4; j++) {
            #pragma unroll
            for (int nj = 0; nj < 4; nj++) {
                uint32_t vh4[4];
                uint32_t boff = ((j * 16 + (lane & 15)) * FSTR +
                                 (nj * 2 + ((lane >> 4) & 1)) * 8) * 2;
                LDSM_X4T(vh4[0], vh4[1], vh4[2], vh4[3], smVh + boff);
                MMA16816(oacc[nj * 2],     aH[j], vh4[0], vh4[1]);
                MMA16816(oacc[nj * 2],     aL[j], vh4[0], vh4[1]);
                MMA16816(oacc[nj * 2 + 1], aH[j], vh4[2], vh4[3]);
                MMA16816(oacc[nj * 2 + 1], aL[j], vh4[2], vh4[3]);
            }
        }
    }

    // ---- epilogue: /l, write f16 hi/lo ----
    {
        float inv0 = 1.0f / lstat0;
        float inv1 = 1.0f / lstat1;
        size_t row0 = (size_t)(b * T_ + qr0) * C_ + h * HD_;
        size_t row1 = (size_t)(b * T_ + qr1) * C_ + h * HD_;
        #pragma unroll
        for (int ni = 0; ni < 8; ni++) {
            int c = ni * 8 + c2;
            uint32_t h0, l0, h1, l1;
            split2h(oacc[ni][0] * inv0, oacc[ni][1] * inv0, h0, l0);
            split2h(oacc[ni][2] * inv1, oacc[ni][3] * inv1, h1, l1);
            *(uint32_t*)&Ohi[row0 + c] = h0;
            *(uint32_t*)&Olo[row0 + c] = l0;
            *(uint32_t*)&Ohi[row1 + c] = h1;
            *(uint32_t*)&Olo[row1 + c] = l1;
        }
    }
}

// ============================================================================
// Launch
// ============================================================================
extern "C" void kernel_launch(void* const* d_in, const int* in_sizes, int n_in,
                              void* d_out, int out_size)
{
    const float* x_q  = (const float*)d_in[0];
    const float* x_r  = (const float*)d_in[1];
    const float* y    = (const float*)d_in[2];
    const int*   mask = (const int*)  d_in[3];
    const float* dist = (const float*)d_in[4];
    const float* Wq   = (const float*)d_in[5];
    const float* bq   = (const float*)d_in[6];
    const float* Wk   = (const float*)d_in[7];
    const float* bk   = (const float*)d_in[8];
    const float* Wv   = (const float*)d_in[9];
    const float* bv   = (const float*)d_in[10];
    const float* Wp   = (const float*)d_in[11];
    const float* bp   = (const float*)d_in[12];
    float* out = (float*)d_out;

    f16 *qh, *ql, *kh, *vh;
    f16 *xqh, *xql, *xrh, *xrl, *yh, *yl, *Oh, *Ol;
    f16 *wqh, *wkh, *wvh, *wph;
    float* wmp;
    cudaGetSymbolAddress((void**)&qh,  g_Qh);
    cudaGetSymbolAddress((void**)&ql,  g_Ql);
    cudaGetSymbolAddress((void**)&kh,  g_Kh);
    cudaGetSymbolAddress((void**)&vh,  g_Vh);
    cudaGetSymbolAddress((void**)&xqh, g_xqh);
    cudaGetSymbolAddress((void**)&xql, g_xql);
    cudaGetSymbolAddress((void**)&xrh, g_xrh);
    cudaGetSymbolAddress((void**)&xrl, g_xrl);
    cudaGetSymbolAddress((void**)&yh,  g_yh);
    cudaGetSymbolAddress((void**)&yl,  g_yl);
    cudaGetSymbolAddress((void**)&Oh,  g_Oh);
    cudaGetSymbolAddress((void**)&Ol,  g_Ol);
    cudaGetSymbolAddress((void**)&wqh, g_Wqh);
    cudaGetSymbolAddress((void**)&wkh, g_Wkh);
    cudaGetSymbolAddress((void**)&wvh, g_Wvh);
    cudaGetSymbolAddress((void**)&wph, g_Wph);
    cudaGetSymbolAddress((void**)&wmp, g_wm);

    cudaFuncSetAttribute(gemm_mma_kernel,
                         cudaFuncAttributeMaxDynamicSharedMemorySize, GEMM_SMEM);
    cudaFuncSetAttribute(flash_mma_kernel,
                         cudaFuncAttributeMaxDynamicSharedMemorySize, FLASH_SMEM);

    // ---- split activations (hi/lo), quantize weights (single), build wm ----
    const int MC4 = M_ * C_ / 4;
    const int CC4 = C_ * C_ / 4;
    split_kernel<<<MC4 / 256, 256>>>((const float4*)x_q, (uint2*)xqh, (uint2*)xql, MC4);
    split_kernel<<<MC4 / 256, 256>>>((const float4*)x_r, (uint2*)xrh, (uint2*)xrl, MC4);
    split_kernel<<<NI_ * MC4 / 256, 256>>>((const float4*)y, (uint2*)yh, (uint2*)yl, NI_ * MC4);
    quant_kernel<<<CC4 / 256, 256>>>((const float4*)Wq, (uint2*)wqh, CC4);
    quant_kernel<<<CC4 / 256, 256>>>((const float4*)Wk, (uint2*)wkh, CC4);
    quant_kernel<<<NI_ * CC4 / 256, 256>>>((const float4*)Wv, (uint2*)wvh, NI_ * CC4);
    quant_kernel<<<CC4 / 256, 256>>>((const float4*)Wp, (uint2*)wph, CC4);
    {
        const int n2 = B_ * T_ * T_ / 2;
        wm_kernel<<<(n2 + 255) / 256, 256>>>((const int2*)mask,
                                             (const float2*)dist,
                                             (float2*)wmp, n2);
    }

    dim3 gblk(256);
    dim3 ggrd(C_ / 128, M_ / 128);       // (8, 32) = 256 CTAs

    // projections: Q -> hi/lo, K -> single, V -> single
    gemm_mma_kernel<<<ggrd, gblk, GEMM_SMEM>>>(xqh, xql, wqh, bq,
                                               nullptr, qh, ql, 1, 0, 0, 1);
    gemm_mma_kernel<<<ggrd, gblk, GEMM_SMEM>>>(xrh, xrl, wkh, bk,
                                               nullptr, kh, nullptr, 1, 0, 0, 2);
    gemm_mma_kernel<<<ggrd, gblk, GEMM_SMEM>>>(yh, yl, wvh, bv,
                                               nullptr, vh, nullptr, NI_,
                                               (size_t)M_ * C_, (size_t)C_ * C_, 2);

    dim3 fgrd(B_ * H_, T_ / FQ);         // (32, 16)
    flash_mma_kernel<<<fgrd, 256, FLASH_SMEM>>>(qh, ql, kh, vh, wmp, Oh, Ol);

    // out projection -> fp32
    gemm_mma_kernel<<<ggrd, gblk, GEMM_SMEM>>>(Oh, Ol, wph, bp,
                                               out, nullptr, nullptr, 1, 0, 0, 0);
}

// round 14
// speedup vs baseline: 1.0714x; 1.0122x over previous
#include <cuda_runtime.h>
#include <cuda_fp16.h>
#include <cstdint>

// Problem shape (fixed by dataset)
#define B_  2
#define T_  2048
#define C_  1024
#define H_  16
#define HD_ 64
#define NI_ 3
#define M_  (B_ * T_)
#define NEG_ (-1e9f)

typedef __half f16;

// -------- scratch (device globals; no allocation allowed) --------
__device__ f16 g_Qh[(size_t)M_ * C_],       g_Ql[(size_t)M_ * C_];
__device__ f16 g_Kh[(size_t)M_ * C_];
__device__ f16 g_Vh[(size_t)M_ * C_];
__device__ f16 g_xqh[(size_t)M_ * C_],      g_xql[(size_t)M_ * C_];
__device__ f16 g_xrh[(size_t)M_ * C_],      g_xrl[(size_t)M_ * C_];
__device__ f16 g_yh [(size_t)NI_ * M_ * C_], g_yl [(size_t)NI_ * M_ * C_];
__device__ f16 g_Oh [(size_t)M_ * C_],      g_Ol [(size_t)M_ * C_];
__device__ f16 g_Wqh[(size_t)C_ * C_];
__device__ f16 g_Wkh[(size_t)C_ * C_];
__device__ f16 g_Wvh[(size_t)NI_ * C_ * C_];
__device__ f16 g_Wph[(size_t)C_ * C_];
__device__ float g_wm[(size_t)B_ * T_ * T_];  // mask? exp(-4d^2) : -1

// ============================================================================
// helpers
// ============================================================================
__device__ __forceinline__ uint32_t smem_u32(const void* p) {
    uint32_t a;
    asm("{ .reg .u64 t; cvta.to.shared.u64 t, %1; cvt.u32.u64 %0, t; }"
        : "=r"(a) : "l"(p));
    return a;
}
__device__ __forceinline__ uint32_t pack_h2(float a, float b) {
    f16 h0 = __float2half_rn(a);
    f16 h1 = __float2half_rn(b);
    return ((uint32_t)__half_as_ushort(h1) << 16) | __half_as_ushort(h0);
}
__device__ __forceinline__ void split2h(float a, float b, uint32_t& hi, uint32_t& lo) {
    f16 h0 = __float2half_rn(a);
    f16 h1 = __float2half_rn(b);
    hi = ((uint32_t)__half_as_ushort(h1) << 16) | __half_as_ushort(h0);
    lo = pack_h2(a - __half2float(h0), b - __half2float(h1));
}

#define CP_ASYNC16(dst, src) \
    asm volatile("cp.async.cg.shared.global [%0], [%1], 16;" :: "r"(dst), "l"(src))
#define CP_COMMIT() asm volatile("cp.async.commit_group;" ::: "memory")
#define CP_WAIT(n)  asm volatile("cp.async.wait_group %0;" :: "n"(n) : "memory")

#define LDSM_X4(r0, r1, r2, r3, addr) \
    asm volatile("ldmatrix.sync.aligned.m8n8.x4.shared.b16 {%0,%1,%2,%3}, [%4];" \
                 : "=r"(r0), "=r"(r1), "=r"(r2), "=r"(r3) : "r"(addr))
#define LDSM_X4T(r0, r1, r2, r3, addr) \
    asm volatile("ldmatrix.sync.aligned.m8n8.x4.trans.shared.b16 {%0,%1,%2,%3}, [%4];" \
                 : "=r"(r0), "=r"(r1), "=r"(r2), "=r"(r3) : "r"(addr))

#define MMA16816(d, a, b0, b1) \
    asm volatile("mma.sync.aligned.m16n8k16.row.col.f32.f16.f16.f32 " \
                 "{%0,%1,%2,%3}, {%4,%5,%6,%7}, {%8,%9}, {%0,%1,%2,%3};" \
                 : "+f"((d)[0]), "+f"((d)[1]), "+f"((d)[2]), "+f"((d)[3]) \
                 : "r"((a)[0]), "r"((a)[1]), "r"((a)[2]), "r"((a)[3]), \
                   "r"(b0), "r"(b1))

// ============================================================================
// split kernel (MLP=4): fp32 -> f16 hi + f16 lo.  4 float4 groups per thread.
// ============================================================================
__global__ __launch_bounds__(256) void split_kernel(
    const float4* __restrict__ in, uint2* __restrict__ hi,
    uint2* __restrict__ lo, int n4)
{
    int base = blockIdx.x * 1024 + threadIdx.x;
    float4 f[4];
    #pragma unroll
    for (int u = 0; u < 4; u++) f[u] = in[base + u * 256];
    #pragma unroll
    for (int u = 0; u < 4; u++) {
        uint32_t h0, l0, h1, l1;
        split2h(f[u].x, f[u].y, h0, l0);
        split2h(f[u].z, f[u].w, h1, l1);
        hi[base + u * 256] = make_uint2(h0, h1);
        lo[base + u * 256] = make_uint2(l0, l1);
    }
}

// quant kernel (MLP=4): fp32 -> single f16
__global__ __launch_bounds__(256) void quant_kernel(
    const float4* __restrict__ in, uint2* __restrict__ hi, int n4)
{
    int base = blockIdx.x * 1024 + threadIdx.x;
    float4 f[4];
    #pragma unroll
    for (int u = 0; u < 4; u++) f[u] = in[base + u * 256];
    #pragma unroll
    for (int u = 0; u < 4; u++)
        hi[base + u * 256] = make_uint2(pack_h2(f[u].x, f[u].y),
                                        pack_h2(f[u].z, f[u].w));
}

// ============================================================================
// wm kernel (MLP=4): wm = mask ? exp(-4 d^2) : -1.  int4/float4, 4 per thread.
// ============================================================================
__global__ __launch_bounds__(256) void wm_kernel(
    const int4* __restrict__ mask, const float4* __restrict__ dist,
    float4* __restrict__ wm, int n4)
{
    int base = blockIdx.x * 1024 + threadIdx.x;
    int4 m[4]; float4 d[4];
    #pragma unroll
    for (int u = 0; u < 4; u++) m[u] = mask[base + u * 256];
    #pragma unroll
    for (int u = 0; u < 4; u++) d[u] = dist[base + u * 256];
    #pragma unroll
    for (int u = 0; u < 4; u++) {
        float4 w;
        w.x = m[u].x ? __expf(-4.0f * d[u].x * d[u].x) : -1.0f;
        w.y = m[u].y ? __expf(-4.0f * d[u].y * d[u].y) : -1.0f;
        w.z = m[u].z ? __expf(-4.0f * d[u].z * d[u].z) : -1.0f;
        w.w = m[u].w ? __expf(-4.0f * d[u].w * d[u].w) : -1.0f;
        wm[base + u * 256] = w;
    }
}

// ============================================================================
// fp16 2-mma GEMM via mma.sync.m16n8k16, 2-stage pipeline, 2 CTAs/SM.
//   C = sum_n (A_n_hi + A_n_lo) @ W_n_hi + sum_n bias_n[N]
// 128x128 CTA tile, 8 warps (2m x 4n).
// outmode 0: fp32 to C.  1: f16 hi/lo to Chi/Clo.  2: single f16 to Chi.
// ============================================================================
#define ASTR 72
#define WSTR 136
#define BKC  64
#define A_BYTES (128 * ASTR * 2)                   // 18432
#define W_BYTES (64 * WSTR * 2)                    // 17408
#define BUF_BYTES (2 * A_BYTES + W_BYTES)          // 54272
#define SMB_BUF 1024
#define GEMM_SMEM (SMB_BUF + 2 * BUF_BYTES)        // 109568 -> 2 CTAs/SM

__device__ __forceinline__ void load_chunk(
    uint32_t sbuf, const f16* __restrict__ Ah, const f16* __restrict__ Al,
    const f16* __restrict__ Wh, int bm, int bn, int k0, int tid)
{
    #pragma unroll
    for (int v = 0; v < 4; v++) {
        int idx = tid + v * 256;
        int r = idx >> 3, c = idx & 7;
        size_t go = (size_t)(bm + r) * C_ + k0 + c * 8;
        uint32_t so = sbuf + r * (ASTR * 2) + c * 16;
        CP_ASYNC16(so, Ah + go);
        CP_ASYNC16(so + A_BYTES, Al + go);
    }
    #pragma unroll
    for (int v = 0; v < 4; v++) {
        int idx = tid + v * 256;
        int r = idx >> 4, c = idx & 15;
        size_t go = (size_t)(k0 + r) * C_ + bn + c * 8;
        uint32_t so = sbuf + 2 * A_BYTES + r * (WSTR * 2) + c * 16;
        CP_ASYNC16(so, Wh + go);
    }
}

__device__ __forceinline__ void compute_chunk(
    uint32_t sbuf, int wm_, int wn, int lane, float acc[4][4][4])
{
    const uint32_t smAh = sbuf;
    const uint32_t smAl = sbuf + A_BYTES;
    const uint32_t smWh = sbuf + 2 * A_BYTES;
    const int m0 = wm_ * 64, n0 = wn * 32;
    const int ar = lane & 15;
    const int ac = (lane >> 4) << 3;

    #pragma unroll
    for (int ks = 0; ks < 4; ks++) {
        const int kk = ks * 16;
        uint32_t ah[4][4], al[4][4], bh[2][4];
        #pragma unroll
        for (int mi = 0; mi < 4; mi++) {
            uint32_t off = ((m0 + mi * 16 + ar) * ASTR + kk + ac) * 2;
            LDSM_X4(ah[mi][0], ah[mi][1], ah[mi][2], ah[mi][3], smAh + off);
            LDSM_X4(al[mi][0], al[mi][1], al[mi][2], al[mi][3], smAl + off);
        }
        #pragma unroll
        for (int nj = 0; nj < 2; nj++) {
            uint32_t off = ((kk + ar) * WSTR + n0 + nj * 16 +
                            ((lane >> 4) & 1) * 8) * 2;
            LDSM_X4T(bh[nj][0], bh[nj][1], bh[nj][2], bh[nj][3], smWh + off);
        }
        #pragma unroll
        for (int mi = 0; mi < 4; mi++)
            #pragma unroll
            for (int nj = 0; nj < 2; nj++) {
                MMA16816(acc[mi][nj * 2],     ah[mi], bh[nj][0], bh[nj][1]);
                MMA16816(acc[mi][nj * 2],     al[mi], bh[nj][0], bh[nj][1]);
                MMA16816(acc[mi][nj * 2 + 1], ah[mi], bh[nj][2], bh[nj][3]);
                MMA16816(acc[mi][nj * 2 + 1], al[mi], bh[nj][2], bh[nj][3]);
            }
    }
}

__global__ __launch_bounds__(256, 2) void gemm_mma_kernel(
    const f16* __restrict__ Ah, const f16* __restrict__ Al,
    const f16* __restrict__ Wh,
    const float* __restrict__ bias, float* __restrict__ C,
    f16* __restrict__ Chi, f16* __restrict__ Clo,
    int nmat, size_t strideA, size_t strideW, int outmode)
{
    extern __shared__ char smc[];
    const uint32_t smb = smem_u32(smc);
    float* s_bias = (float*)smc;

    const int tid = threadIdx.x;
    const int lane = tid & 31;
    const int wid = tid >> 5;
    const int wm_ = wid & 1;
    const int wn = wid >> 1;
    const int bm = blockIdx.y * 128;
    const int bn = blockIdx.x * 128;

    if (tid < 128) {
        float bs = 0.f;
        for (int n = 0; n < nmat; n++) bs += bias[(size_t)n * C_ + bn + tid];
        s_bias[tid] = bs;
    }

    float acc[4][4][4];
    #pragma unroll
    for (int mi = 0; mi < 4; mi++)
        #pragma unroll
        for (int ni = 0; ni < 4; ni++)
            #pragma unroll
            for (int r = 0; r < 4; r++) acc[mi][ni][r] = 0.f;

    const int NC = nmat * (C_ / BKC);

    // prologue: chunk 0
    load_chunk(smb + SMB_BUF, Ah, Al, Wh, bm, bn, 0, tid);
    CP_COMMIT();

    for (int c = 0; c < NC; c++) {
        if (c + 1 < NC) {
            int cc = c + 1;
            int nm = cc >> 4;
            int k0 = (cc & 15) * BKC;
            load_chunk(smb + SMB_BUF + (cc & 1) * BUF_BYTES,
                       Ah + (size_t)nm * strideA, Al + (size_t)nm * strideA,
                       Wh + (size_t)nm * strideW, bm, bn, k0, tid);
            CP_COMMIT();
            CP_WAIT(1);
        } else {
            CP_WAIT(0);
        }
        __syncthreads();
        compute_chunk(smb + SMB_BUF + (c & 1) * BUF_BYTES, wm_, wn, lane, acc);
        __syncthreads();
    }

    const int r0 = bm + wm_ * 64 + (lane >> 2);
    const int c0rel = wn * 32 + 2 * (lane & 3);
    #pragma unroll
    for (int mi = 0; mi < 4; mi++) {
        #pragma unroll
        for (int ni = 0; ni < 4; ni++) {
            int crel = c0rel + ni * 8;
            float b0 = s_bias[crel], b1 = s_bias[crel + 1];
            int row = r0 + mi * 16;
            float a0 = acc[mi][ni][0] + b0, a1 = acc[mi][ni][1] + b1;
            float a2 = acc[mi][ni][2] + b0, a3 = acc[mi][ni][3] + b1;
            if (outmode == 0) {
                *(float2*)&C[(size_t)row * C_ + bn + crel] = make_float2(a0, a1);
                *(float2*)&C[(size_t)(row + 8) * C_ + bn + crel] = make_float2(a2, a3);
            } else if (outmode == 1) {
                uint32_t h0, l0, h1, l1;
                split2h(a0, a1, h0, l0);
                split2h(a2, a3, h1, l1);
                *(uint32_t*)&Chi[(size_t)row * C_ + bn + crel] = h0;
                *(uint32_t*)&Clo[(size_t)row * C_ + bn + crel] = l0;
                *(uint32_t*)&Chi[(size_t)(row + 8) * C_ + bn + crel] = h1;
                *(uint32_t*)&Clo[(size_t)(row + 8) * C_ + bn + crel] = l1;
            } else {
                *(uint32_t*)&Chi[(size_t)row * C_ + bn + crel] = pack_h2(a0, a1);
                *(uint32_t*)&Chi[(size_t)(row + 8) * C_ + bn + crel] = pack_h2(a2, a3);
            }
        }
    }
}

// ============================================================================
// Flash attention: fp16 2-mma, register softmax, precomputed wm, 3-stage KV,
// 2 CTAs/SM. Q and P are the exact (hi/lo) side; K and V single-f16.
// CTA: 128 q-rows, kv chunks of 64, 8 warps (16 q-rows each).
// ============================================================================
#define FQ 128
#define FS 64
#define FSTR 72
#define OFF_QH 0
#define OFF_QL 18432
#define OFF_BUF 36864
#define KV_BUF_BYTES 18432                         // K 9216 + V 9216
#define FLASH_SMEM (OFF_BUF + 3 * KV_BUF_BYTES)    // 92160 -> 2 CTAs/SM

__device__ __forceinline__ void flash_load_kv(
    uint32_t bb, const f16* __restrict__ Kh, const f16* __restrict__ Vh,
    int b, int h, int s0, int tid)
{
    #pragma unroll
    for (int v = 0; v < 2; v++) {
        int idx = tid + v * 256;
        int r = idx >> 3, c = idx & 7;
        size_t go = (size_t)(b * T_ + s0 + r) * C_ + h * HD_ + c * 8;
        uint32_t so = bb + r * (FSTR * 2) + c * 16;
        CP_ASYNC16(so,        Kh + go);
        CP_ASYNC16(so + 9216, Vh + go);
    }
}

__global__ __launch_bounds__(256, 2) void flash_mma_kernel(
    const f16* __restrict__ Qh, const f16* __restrict__ Ql,
    const f16* __restrict__ Kh, const f16* __restrict__ Vh,
    const float* __restrict__ wm, f16* __restrict__ Ohi,
    f16* __restrict__ Olo)
{
    extern __shared__ char smc[];
    const uint32_t smb = smem_u32(smc);

    const int bh  = blockIdx.x;
    const int b   = bh >> 4;
    const int h   = bh & 15;
    const int t10 = blockIdx.y * FQ;
    const int tid = threadIdx.x;
    const int lane = tid & 31;
    const int wid = tid >> 5;
    const int m0 = wid * 16;
    const int g  = lane >> 2;
    const int c2 = (lane & 3) * 2;

    const int qr0 = t10 + m0 + g;
    const int qr1 = qr0 + 8;
    const float* wrow0 = &wm[(size_t)(b * T_ + qr0) * T_];
    const float* wrow1 = &wm[(size_t)(b * T_ + qr1) * T_];

    // ---- load Q tile (hi/lo) ----
    #pragma unroll
    for (int v = 0; v < 4; v++) {
        int idx = tid + v * 256;
        int r = idx >> 3, c = idx & 7;
        size_t go = (size_t)(b * T_ + t10 + r) * C_ + h * HD_ + c * 8;
        uint32_t so = smb + r * (FSTR * 2) + c * 16;
        CP_ASYNC16(so + OFF_QH, Qh + go);
        CP_ASYNC16(so + OFF_QL, Ql + go);
    }
    CP_COMMIT();
    // ---- kv chunks 0, 1 ----
    flash_load_kv(smb + OFF_BUF, Kh, Vh, b, h, 0, tid);
    CP_COMMIT();
    flash_load_kv(smb + OFF_BUF + KV_BUF_BYTES, Kh, Vh, b, h, FS, tid);
    CP_COMMIT();

    float mstat0 = -3.0e38f, mstat1 = -3.0e38f;
    float lstat0 = 0.f, lstat1 = 0.f;

    float oacc[8][4];
    #pragma unroll
    for (int ni = 0; ni < 8; ni++)
        #pragma unroll
        for (int r = 0; r < 4; r++) oacc[ni][r] = 0.f;

    const int NITER = T_ / FS;           // 32

    for (int it = 0; it < NITER; it++) {
        if (it + 1 < NITER) { CP_WAIT(1); } else { CP_WAIT(0); }
        __syncthreads();
        if (it + 2 < NITER) {
            flash_load_kv(smb + OFF_BUF + ((it + 2) % 3) * KV_BUF_BYTES,
                          Kh, Vh, b, h, (it + 2) * FS, tid);
            CP_COMMIT();
        }

        const int s0 = it * FS;
        const uint32_t bb = smb + OFF_BUF + (it % 3) * KV_BUF_BYTES;
        const uint32_t smKh = bb;
        const uint32_t smVh = bb + 9216;

        // ---- S = (Qh + Ql) K^T ----
        float sacc[8][4];
        #pragma unroll
        for (int ni = 0; ni < 8; ni++)
            #pragma unroll
            for (int r = 0; r < 4; r++) sacc[ni][r] = 0.f;

        #pragma unroll
        for (int ks = 0; ks < 4; ks++) {
            const int k0 = ks * 16;
            uint32_t qh[4], ql[4];
            uint32_t aoff = ((m0 + (lane & 15)) * FSTR + k0 + ((lane >> 4) << 3)) * 2;
            LDSM_X4(qh[0], qh[1], qh[2], qh[3], smb + OFF_QH + aoff);
            LDSM_X4(ql[0], ql[1], ql[2], ql[3], smb + OFF_QL + aoff);
            #pragma unroll
            for (int nj = 0; nj < 4; nj++) {
                uint32_t kh4[4];
                uint32_t boff = ((nj * 16 + (lane & 7) + ((lane >> 4) << 3)) * FSTR +
                                 k0 + ((lane >> 3) & 1) * 8) * 2;
                LDSM_X4(kh4[0], kh4[1], kh4[2], kh4[3], smKh + boff);
                MMA16816(sacc[nj * 2],     qh, kh4[0], kh4[1]);
                MMA16816(sacc[nj * 2],     ql, kh4[0], kh4[1]);
                MMA16816(sacc[nj * 2 + 1], qh, kh4[2], kh4[3]);
                MMA16816(sacc[nj * 2 + 1], ql, kh4[2], kh4[3]);
            }
        }

        // ---- wm load: scale + mask via sign ----
        float wreg[8][4];
        #pragma unroll
        for (int ni = 0; ni < 8; ni++) {
            int s = s0 + ni * 8 + c2;
            float2 w0 = *(const float2*)&wrow0[s];
            float2 w1 = *(const float2*)&wrow1[s];
            wreg[ni][0] = w0.x; wreg[ni][1] = w0.y;
            wreg[ni][2] = w1.x; wreg[ni][3] = w1.y;
            sacc[ni][0] = w0.x > 0.f ? sacc[ni][0] * 0.125f : NEG_;
            sacc[ni][1] = w0.y > 0.f ? sacc[ni][1] * 0.125f : NEG_;
            sacc[ni][2] = w1.x > 0.f ? sacc[ni][2] * 0.125f : NEG_;
            sacc[ni][3] = w1.y > 0.f ? sacc[ni][3] * 0.125f : NEG_;
        }

        // ---- row max ----
        float mx0 = -3.0e38f, mx1 = -3.0e38f;
        #pragma unroll
        for (int ni = 0; ni < 8; ni++) {
            mx0 = fmaxf(mx0, fmaxf(sacc[ni][0], sacc[ni][1]));
            mx1 = fmaxf(mx1, fmaxf(sacc[ni][2], sacc[ni][3]));
        }
        mx0 = fmaxf(mx0, __shfl_xor_sync(0xffffffff, mx0, 1));
        mx0 = fmaxf(mx0, __shfl_xor_sync(0xffffffff, mx0, 2));
        mx1 = fmaxf(mx1, __shfl_xor_sync(0xffffffff, mx1, 1));
        mx1 = fmaxf(mx1, __shfl_xor_sync(0xffffffff, mx1, 2));

        float mnew0 = fmaxf(mstat0, mx0);
        float mnew1 = fmaxf(mstat1, mx1);
        float fr0 = __expf(mstat0 - mnew0);
        float fr1 = __expf(mstat1 - mnew1);
        mstat0 = mnew0; mstat1 = mnew1;

        // ---- exp + row sum ----
        float sum0 = 0.f, sum1 = 0.f;
        #pragma unroll
        for (int ni = 0; ni < 8; ni++) {
            sacc[ni][0] = __expf(sacc[ni][0] - mnew0);
            sacc[ni][1] = __expf(sacc[ni][1] - mnew0);
            sacc[ni][2] = __expf(sacc[ni][2] - mnew1);
            sacc[ni][3] = __expf(sacc[ni][3] - mnew1);
            sum0 += sacc[ni][0] + sacc[ni][1];
            sum1 += sacc[ni][2] + sacc[ni][3];
        }
        sum0 += __shfl_xor_sync(0xffffffff, sum0, 1);
        sum0 += __shfl_xor_sync(0xffffffff, sum0, 2);
        sum1 += __shfl_xor_sync(0xffffffff, sum1, 1);
        sum1 += __shfl_xor_sync(0xffffffff, sum1, 2);
        lstat0 = lstat0 * fr0 + sum0;
        lstat1 = lstat1 * fr1 + sum1;

        // ---- numerator modulation + pack P fragments (hi/lo, exact) ----
        uint32_t aH[4][4], aL[4][4];
        #pragma unroll
        for (int j = 0; j < 4; j++) {
            #pragma unroll
            for (int half = 0; half < 2; half++) {
                int ni = 2 * j + half;
                float p00 = sacc[ni][0] * wreg[ni][0];
                float p01 = sacc[ni][1] * wreg[ni][1];
                float p10 = sacc[ni][2] * wreg[ni][2];
                float p11 = sacc[ni][3] * wreg[ni][3];
                split2h(p00, p01, aH[j][half * 2 + 0], aL[j][half * 2 + 0]);
                split2h(p10, p11, aH[j][half * 2 + 1], aL[j][half * 2 + 1]);
            }
        }

        // ---- rescale O, then O += (Ph + Pl) @ V ----
        #pragma unroll
        for (int ni = 0; ni < 8; ni++) {
            oacc[ni][0] *= fr0; oacc[ni][1] *= fr0;
            oacc[ni][2] *= fr1; oacc[ni][3] *= fr1;
        }
        #pragma unroll
        for (int j = 0; j < 4; j++) {
            #pragma unroll
            for (int nj = 0; nj < 4; nj++) {
                uint32_t vh4[4];
                uint32_t boff = ((j * 16 + (lane & 15)) * FSTR +
                                 (nj * 2 + ((lane >> 4) & 1)) * 8) * 2;
                LDSM_X4T(vh4[0], vh4[1], vh4[2], vh4[3], smVh + boff);
                MMA16816(oacc[nj * 2],     aH[j], vh4[0], vh4[1]);
                MMA16816(oacc[nj * 2],     aL[j], vh4[0], vh4[1]);
                MMA16816(oacc[nj * 2 + 1], aH[j], vh4[2], vh4[3]);
                MMA16816(oacc[nj * 2 + 1], aL[j], vh4[2], vh4[3]);
            }
        }
    }

    // ---- epilogue: /l, write f16 hi/lo ----
    {
        float inv0 = 1.0f / lstat0;
        float inv1 = 1.0f / lstat1;
        size_t row0 = (size_t)(b * T_ + qr0) * C_ + h * HD_;
        size_t row1 = (size_t)(b * T_ + qr1) * C_ + h * HD_;
        #pragma unroll
        for (int ni = 0; ni < 8; ni++) {
            int c = ni * 8 + c2;
            uint32_t h0, l0, h1, l1;
            split2h(oacc[ni][0] * inv0, oacc[ni][1] * inv0, h0, l0);
            split2h(oacc[ni][2] * inv1, oacc[ni][3] * inv1, h1, l1);
            *(uint32_t*)&Ohi[row0 + c] = h0;
            *(uint32_t*)&Olo[row0 + c] = l0;
            *(uint32_t*)&Ohi[row1 + c] = h1;
            *(uint32_t*)&Olo[row1 + c] = l1;
        }
    }
}

// ============================================================================
// Launch
// ============================================================================
extern "C" void kernel_launch(void* const* d_in, const int* in_sizes, int n_in,
                              void* d_out, int out_size)
{
    const float* x_q  = (const float*)d_in[0];
    const float* x_r  = (const float*)d_in[1];
    const float* y    = (const float*)d_in[2];
    const int*   mask = (const int*)  d_in[3];
    const float* dist = (const float*)d_in[4];
    const float* Wq   = (const float*)d_in[5];
    const float* bq   = (const float*)d_in[6];
    const float* Wk   = (const float*)d_in[7];
    const float* bk   = (const float*)d_in[8];
    const float* Wv   = (const float*)d_in[9];
    const float* bv   = (const float*)d_in[10];
    const float* Wp   = (const float*)d_in[11];
    const float* bp   = (const float*)d_in[12];
    float* out = (float*)d_out;

    f16 *qh, *ql, *kh, *vh;
    f16 *xqh, *xql, *xrh, *xrl, *yh, *yl, *Oh, *Ol;
    f16 *wqh, *wkh, *wvh, *wph;
    float* wmp;
    cudaGetSymbolAddress((void**)&qh,  g_Qh);
    cudaGetSymbolAddress((void**)&ql,  g_Ql);
    cudaGetSymbolAddress((void**)&kh,  g_Kh);
    cudaGetSymbolAddress((void**)&vh,  g_Vh);
    cudaGetSymbolAddress((void**)&xqh, g_xqh);
    cudaGetSymbolAddress((void**)&xql, g_xql);
    cudaGetSymbolAddress((void**)&xrh, g_xrh);
    cudaGetSymbolAddress((void**)&xrl, g_xrl);
    cudaGetSymbolAddress((void**)&yh,  g_yh);
    cudaGetSymbolAddress((void**)&yl,  g_yl);
    cudaGetSymbolAddress((void**)&Oh,  g_Oh);
    cudaGetSymbolAddress((void**)&Ol,  g_Ol);
    cudaGetSymbolAddress((void**)&wqh, g_Wqh);
    cudaGetSymbolAddress((void**)&wkh, g_Wkh);
    cudaGetSymbolAddress((void**)&wvh, g_Wvh);
    cudaGetSymbolAddress((void**)&wph, g_Wph);
    cudaGetSymbolAddress((void**)&wmp, g_wm);

    cudaFuncSetAttribute(gemm_mma_kernel,
                         cudaFuncAttributeMaxDynamicSharedMemorySize, GEMM_SMEM);
    cudaFuncSetAttribute(flash_mma_kernel,
                         cudaFuncAttributeMaxDynamicSharedMemorySize, FLASH_SMEM);

    // ---- split activations (hi/lo), quantize weights (single), build wm ----
    // All kernels process 4 float4-groups per thread (MLP=4).
    const int MC4 = M_ * C_ / 4;          // 1,048,576
    const int CC4 = C_ * C_ / 4;          // 262,144
    split_kernel<<<MC4 / 1024, 256>>>((const float4*)x_q, (uint2*)xqh, (uint2*)xql, MC4);
    split_kernel<<<MC4 / 1024, 256>>>((const float4*)x_r, (uint2*)xrh, (uint2*)xrl, MC4);
    split_kernel<<<NI_ * MC4 / 1024, 256>>>((const float4*)y, (uint2*)yh, (uint2*)yl, NI_ * MC4);
    quant_kernel<<<CC4 / 1024, 256>>>((const float4*)Wq, (uint2*)wqh, CC4);
    quant_kernel<<<CC4 / 1024, 256>>>((const float4*)Wk, (uint2*)wkh, CC4);
    quant_kernel<<<NI_ * CC4 / 1024, 256>>>((const float4*)Wv, (uint2*)wvh, NI_ * CC4);
    quant_kernel<<<CC4 / 1024, 256>>>((const float4*)Wp, (uint2*)wph, CC4);
    {
        const int n4 = B_ * T_ * T_ / 4;  // 2,097,152
        wm_kernel<<<n4 / 1024, 256>>>((const int4*)mask, (const float4*)dist,
                                      (float4*)wmp, n4);
    }

    dim3 gblk(256);
    dim3 ggrd(C_ / 128, M_ / 128);       // (8, 32) = 256 CTAs

    // projections: Q -> hi/lo, K -> single, V -> single
    gemm_mma_kernel<<<ggrd, gblk, GEMM_SMEM>>>(xqh, xql, wqh, bq,
                                               nullptr, qh, ql, 1, 0, 0, 1);
    gemm_mma_kernel<<<ggrd, gblk, GEMM_SMEM>>>(xrh, xrl, wkh, bk,
                                               nullptr, kh, nullptr, 1, 0, 0, 2);
    gemm_mma_kernel<<<ggrd, gblk, GEMM_SMEM>>>(yh, yl, wvh, bv,
                                               nullptr, vh, nullptr, NI_,
                                               (size_t)M_ * C_, (size_t)C_ * C_, 2);

    dim3 fgrd(B_ * H_, T_ / FQ);         // (32, 16)
    flash_mma_kernel<<<fgrd, 256, FLASH_SMEM>>>(qh, ql, kh, vh, wmp, Oh, Ol);

    // out projection -> fp32
    gemm_mma_kernel<<<ggrd, gblk, GEMM_SMEM>>>(Oh, Ol, wph, bp,
                                               out, nullptr, nullptr, 1, 0, 0, 0);
}

// round 15
// speedup vs baseline: 1.5613x; 1.4572x over previous
#include <cuda_runtime.h>
#include <cuda_fp16.h>
#include <cstdint>

// Problem shape (fixed by dataset)
#define B_  2
#define T_  2048
#define C_  1024
#define H_  16
#define HD_ 64
#define NI_ 3
#define M_  (B_ * T_)
#define NEG_ (-1e9f)

typedef __half f16;

// -------- scratch (device globals; no allocation allowed) --------
__device__ f16 g_Q[(size_t)M_ * C_];
__device__ f16 g_K[(size_t)M_ * C_];
__device__ f16 g_V[(size_t)M_ * C_];
__device__ f16 g_O[(size_t)M_ * C_];
__device__ f16 g_xq[(size_t)M_ * C_];
__device__ f16 g_xr[(size_t)M_ * C_];
__device__ f16 g_y [(size_t)NI_ * M_ * C_];
__device__ f16 g_Wq[(size_t)C_ * C_];
__device__ f16 g_Wk[(size_t)C_ * C_];
__device__ f16 g_Wv[(size_t)NI_ * C_ * C_];
__device__ f16 g_Wp[(size_t)C_ * C_];
__device__ float g_wm[(size_t)B_ * T_ * T_];  // mask? exp(-4d^2) : -1

// ============================================================================
// helpers
// ============================================================================
__device__ __forceinline__ uint32_t smem_u32(const void* p) {
    uint32_t a;
    asm("{ .reg .u64 t; cvta.to.shared.u64 t, %1; cvt.u32.u64 %0, t; }"
        : "=r"(a) : "l"(p));
    return a;
}
__device__ __forceinline__ uint32_t pack_h2(float a, float b) {
    f16 h0 = __float2half_rn(a);
    f16 h1 = __float2half_rn(b);
    return ((uint32_t)__half_as_ushort(h1) << 16) | __half_as_ushort(h0);
}

#define CP_ASYNC16(dst, src) \
    asm volatile("cp.async.cg.shared.global [%0], [%1], 16;" :: "r"(dst), "l"(src))
#define CP_COMMIT() asm volatile("cp.async.commit_group;" ::: "memory")
#define CP_WAIT(n)  asm volatile("cp.async.wait_group %0;" :: "n"(n) : "memory")

#define LDSM_X4(r0, r1, r2, r3, addr) \
    asm volatile("ldmatrix.sync.aligned.m8n8.x4.shared.b16 {%0,%1,%2,%3}, [%4];" \
                 : "=r"(r0), "=r"(r1), "=r"(r2), "=r"(r3) : "r"(addr))
#define LDSM_X4T(r0, r1, r2, r3, addr) \
    asm volatile("ldmatrix.sync.aligned.m8n8.x4.trans.shared.b16 {%0,%1,%2,%3}, [%4];" \
                 : "=r"(r0), "=r"(r1), "=r"(r2), "=r"(r3) : "r"(addr))

#define MMA16816(d, a, b0, b1) \
    asm volatile("mma.sync.aligned.m16n8k16.row.col.f32.f16.f16.f32 " \
                 "{%0,%1,%2,%3}, {%4,%5,%6,%7}, {%8,%9}, {%0,%1,%2,%3};" \
                 : "+f"((d)[0]), "+f"((d)[1]), "+f"((d)[2]), "+f"((d)[3]) \
                 : "r"((a)[0]), "r"((a)[1]), "r"((a)[2]), "r"((a)[3]), \
                   "r"(b0), "r"(b1))

// ============================================================================
// quant kernel (MLP=4): fp32 -> single f16
// ============================================================================
__global__ __launch_bounds__(256) void quant_kernel(
    const float4* __restrict__ in, uint2* __restrict__ hi, int n4)
{
    int base = blockIdx.x * 1024 + threadIdx.x;
    float4 f[4];
    #pragma unroll
    for (int u = 0; u < 4; u++) f[u] = in[base + u * 256];
    #pragma unroll
    for (int u = 0; u < 4; u++)
        hi[base + u * 256] = make_uint2(pack_h2(f[u].x, f[u].y),
                                        pack_h2(f[u].z, f[u].w));
}

// ============================================================================
// wm kernel (MLP=4): wm = mask ? exp(-4 d^2) : -1
// ============================================================================
__global__ __launch_bounds__(256) void wm_kernel(
    const int4* __restrict__ mask, const float4* __restrict__ dist,
    float4* __restrict__ wm, int n4)
{
    int base = blockIdx.x * 1024 + threadIdx.x;
    int4 m[4]; float4 d[4];
    #pragma unroll
    for (int u = 0; u < 4; u++) m[u] = mask[base + u * 256];
    #pragma unroll
    for (int u = 0; u < 4; u++) d[u] = dist[base + u * 256];
    #pragma unroll
    for (int u = 0; u < 4; u++) {
        float4 w;
        w.x = m[u].x ? __expf(-4.0f * d[u].x * d[u].x) : -1.0f;
        w.y = m[u].y ? __expf(-4.0f * d[u].y * d[u].y) : -1.0f;
        w.z = m[u].z ? __expf(-4.0f * d[u].z * d[u].z) : -1.0f;
        w.w = m[u].w ? __expf(-4.0f * d[u].w * d[u].w) : -1.0f;
        wm[base + u * 256] = w;
    }
}

// ============================================================================
// fp16 single-mma GEMM, 3-stage pipeline, 2 CTAs/SM, 128x128 CTA tile.
//   C = sum_n A_n[M,K] @ W_n[K,N] + sum_n bias_n[N]
// 8 warps (2m x 4n). outmode 0: fp32 to C.  1: f16 to Chi.
// ============================================================================
#define ASTR 72
#define WSTR 136
#define BKC  64
#define A_BYTES (128 * ASTR * 2)                   // 18432
#define W_BYTES (64 * WSTR * 2)                    // 17408
#define BUF_BYTES (A_BYTES + W_BYTES)              // 35840
#define SMB_BUF 1024
#define GEMM_SMEM (SMB_BUF + 3 * BUF_BYTES)        // 108544 -> 2 CTAs/SM

__device__ __forceinline__ void load_chunk(
    uint32_t sbuf, const f16* __restrict__ A, const f16* __restrict__ W,
    int bm, int bn, int k0, int tid)
{
    #pragma unroll
    for (int v = 0; v < 4; v++) {
        int idx = tid + v * 256;
        int r = idx >> 3, c = idx & 7;
        size_t go = (size_t)(bm + r) * C_ + k0 + c * 8;
        uint32_t so = sbuf + r * (ASTR * 2) + c * 16;
        CP_ASYNC16(so, A + go);
    }
    #pragma unroll
    for (int v = 0; v < 4; v++) {
        int idx = tid + v * 256;
        int r = idx >> 4, c = idx & 15;
        size_t go = (size_t)(k0 + r) * C_ + bn + c * 8;
        uint32_t so = sbuf + A_BYTES + r * (WSTR * 2) + c * 16;
        CP_ASYNC16(so, W + go);
    }
}

__device__ __forceinline__ void compute_chunk(
    uint32_t sbuf, int wm_, int wn, int lane, float acc[4][4][4])
{
    const uint32_t smA = sbuf;
    const uint32_t smW = sbuf + A_BYTES;
    const int m0 = wm_ * 64, n0 = wn * 32;
    const int ar = lane & 15;
    const int ac = (lane >> 4) << 3;

    #pragma unroll
    for (int ks = 0; ks < 4; ks++) {
        const int kk = ks * 16;
        uint32_t ah[4][4], bh[2][4];
        #pragma unroll
        for (int mi = 0; mi < 4; mi++) {
            uint32_t off = ((m0 + mi * 16 + ar) * ASTR + kk + ac) * 2;
            LDSM_X4(ah[mi][0], ah[mi][1], ah[mi][2], ah[mi][3], smA + off);
        }
        #pragma unroll
        for (int nj = 0; nj < 2; nj++) {
            uint32_t off = ((kk + ar) * WSTR + n0 + nj * 16 +
                            ((lane >> 4) & 1) * 8) * 2;
            LDSM_X4T(bh[nj][0], bh[nj][1], bh[nj][2], bh[nj][3], smW + off);
        }
        #pragma unroll
        for (int mi = 0; mi < 4; mi++)
            #pragma unroll
            for (int nj = 0; nj < 2; nj++) {
                MMA16816(acc[mi][nj * 2],     ah[mi], bh[nj][0], bh[nj][1]);
                MMA16816(acc[mi][nj * 2 + 1], ah[mi], bh[nj][2], bh[nj][3]);
            }
    }
}

__global__ __launch_bounds__(256, 2) void gemm_mma_kernel(
    const f16* __restrict__ A, const f16* __restrict__ W,
    const float* __restrict__ bias, float* __restrict__ C,
    f16* __restrict__ Chi,
    int nmat, size_t strideA, size_t strideW, int outmode)
{
    extern __shared__ char smc[];
    const uint32_t smb = smem_u32(smc);
    float* s_bias = (float*)smc;

    const int tid = threadIdx.x;
    const int lane = tid & 31;
    const int wid = tid >> 5;
    const int wm_ = wid & 1;
    const int wn = wid >> 1;
    const int bm = blockIdx.y * 128;
    const int bn = blockIdx.x * 128;

    if (tid < 128) {
        float bs = 0.f;
        for (int n = 0; n < nmat; n++) bs += bias[(size_t)n * C_ + bn + tid];
        s_bias[tid] = bs;
    }

    float acc[4][4][4];
    #pragma unroll
    for (int mi = 0; mi < 4; mi++)
        #pragma unroll
        for (int ni = 0; ni < 4; ni++)
            #pragma unroll
            for (int r = 0; r < 4; r++) acc[mi][ni][r] = 0.f;

    const int NC = nmat * (C_ / BKC);

    // prologue: chunks 0, 1
    load_chunk(smb + SMB_BUF, A, W, bm, bn, 0, tid);
    CP_COMMIT();
    load_chunk(smb + SMB_BUF + BUF_BYTES, A, W, bm, bn, BKC, tid);
    CP_COMMIT();

    for (int c = 0; c < NC; c++) {
        if (c + 1 < NC) { CP_WAIT(1); } else { CP_WAIT(0); }
        __syncthreads();
        if (c + 2 < NC) {
            int cc = c + 2;
            int nm = cc >> 4;
            int k0 = (cc & 15) * BKC;
            load_chunk(smb + SMB_BUF + (cc % 3) * BUF_BYTES,
                       A + (size_t)nm * strideA,
                       W + (size_t)nm * strideW, bm, bn, k0, tid);
            CP_COMMIT();
        }
        compute_chunk(smb + SMB_BUF + (c % 3) * BUF_BYTES, wm_, wn, lane, acc);
    }

    const int r0 = bm + wm_ * 64 + (lane >> 2);
    const int c0rel = wn * 32 + 2 * (lane & 3);
    #pragma unroll
    for (int mi = 0; mi < 4; mi++) {
        #pragma unroll
        for (int ni = 0; ni < 4; ni++) {
            int crel = c0rel + ni * 8;
            float b0 = s_bias[crel], b1 = s_bias[crel + 1];
            int row = r0 + mi * 16;
            float a0 = acc[mi][ni][0] + b0, a1 = acc[mi][ni][1] + b1;
            float a2 = acc[mi][ni][2] + b0, a3 = acc[mi][ni][3] + b1;
            if (outmode == 0) {
                *(float2*)&C[(size_t)row * C_ + bn + crel] = make_float2(a0, a1);
                *(float2*)&C[(size_t)(row + 8) * C_ + bn + crel] = make_float2(a2, a3);
            } else {
                *(uint32_t*)&Chi[(size_t)row * C_ + bn + crel] = pack_h2(a0, a1);
                *(uint32_t*)&Chi[(size_t)(row + 8) * C_ + bn + crel] = pack_h2(a2, a3);
            }
        }
    }
}

// ============================================================================
// Flash attention: single-fp16 mma, register softmax, precomputed wm,
// 3-stage KV pipeline, 2 CTAs/SM. 128 q-rows, kv chunks of 64, 8 warps.
// ============================================================================
#define FQ 128
#define FS 64
#define FSTR 72
#define OFF_Q 0
#define OFF_BUF 18432
#define KV_BUF_BYTES 18432                         // K 9216 + V 9216
#define FLASH_SMEM (OFF_BUF + 3 * KV_BUF_BYTES)    // 73728 -> 2 CTAs/SM

__device__ __forceinline__ void flash_load_kv(
    uint32_t bb, const f16* __restrict__ K, const f16* __restrict__ V,
    int b, int h, int s0, int tid)
{
    #pragma unroll
    for (int v = 0; v < 2; v++) {
        int idx = tid + v * 256;
        int r = idx >> 3, c = idx & 7;
        size_t go = (size_t)(b * T_ + s0 + r) * C_ + h * HD_ + c * 8;
        uint32_t so = bb + r * (FSTR * 2) + c * 16;
        CP_ASYNC16(so,        K + go);
        CP_ASYNC16(so + 9216, V + go);
    }
}

__global__ __launch_bounds__(256, 2) void flash_mma_kernel(
    const f16* __restrict__ Q, const f16* __restrict__ K,
    const f16* __restrict__ V, const float* __restrict__ wm,
    f16* __restrict__ O)
{
    extern __shared__ char smc[];
    const uint32_t smb = smem_u32(smc);

    const int bh  = blockIdx.x;
    const int b   = bh >> 4;
    const int h   = bh & 15;
    const int t10 = blockIdx.y * FQ;
    const int tid = threadIdx.x;
    const int lane = tid & 31;
    const int wid = tid >> 5;
    const int m0 = wid * 16;
    const int g  = lane >> 2;
    const int c2 = (lane & 3) * 2;

    const int qr0 = t10 + m0 + g;
    const int qr1 = qr0 + 8;
    const float* wrow0 = &wm[(size_t)(b * T_ + qr0) * T_];
    const float* wrow1 = &wm[(size_t)(b * T_ + qr1) * T_];

    // ---- load Q tile (single f16) ----
    #pragma unroll
    for (int v = 0; v < 4; v++) {
        int idx = tid + v * 256;
        int r = idx >> 3, c = idx & 7;
        size_t go = (size_t)(b * T_ + t10 + r) * C_ + h * HD_ + c * 8;
        uint32_t so = smb + OFF_Q + r * (FSTR * 2) + c * 16;
        CP_ASYNC16(so, Q + go);
    }
    CP_COMMIT();
    // ---- kv chunks 0, 1 ----
    flash_load_kv(smb + OFF_BUF, K, V, b, h, 0, tid);
    CP_COMMIT();
    flash_load_kv(smb + OFF_BUF + KV_BUF_BYTES, K, V, b, h, FS, tid);
    CP_COMMIT();

    float mstat0 = -3.0e38f, mstat1 = -3.0e38f;
    float lstat0 = 0.f, lstat1 = 0.f;

    float oacc[8][4];
    #pragma unroll
    for (int ni = 0; ni < 8; ni++)
        #pragma unroll
        for (int r = 0; r < 4; r++) oacc[ni][r] = 0.f;

    const int NITER = T_ / FS;           // 32

    for (int it = 0; it < NITER; it++) {
        if (it + 1 < NITER) { CP_WAIT(1); } else { CP_WAIT(0); }
        __syncthreads();
        if (it + 2 < NITER) {
            flash_load_kv(smb + OFF_BUF + ((it + 2) % 3) * KV_BUF_BYTES,
                          K, V, b, h, (it + 2) * FS, tid);
            CP_COMMIT();
        }

        const int s0 = it * FS;
        const uint32_t bb = smb + OFF_BUF + (it % 3) * KV_BUF_BYTES;
        const uint32_t smK = bb;
        const uint32_t smV = bb + 9216;

        // ---- S = Q K^T (single mma per fragment) ----
        float sacc[8][4];
        #pragma unroll
        for (int ni = 0; ni < 8; ni++)
            #pragma unroll
            for (int r = 0; r < 4; r++) sacc[ni][r] = 0.f;

        #pragma unroll
        for (int ks = 0; ks < 4; ks++) {
            const int k0 = ks * 16;
            uint32_t qf[4];
            uint32_t aoff = (uint32_t)OFF_Q +
                ((m0 + (lane & 15)) * FSTR + k0 + ((lane >> 4) << 3)) * 2;
            LDSM_X4(qf[0], qf[1], qf[2], qf[3], smb + aoff);
            #pragma unroll
            for (int nj = 0; nj < 4; nj++) {
                uint32_t kh4[4];
                uint32_t boff = ((nj * 16 + (lane & 7) + ((lane >> 4) << 3)) * FSTR +
                                 k0 + ((lane >> 3) & 1) * 8) * 2;
                LDSM_X4(kh4[0], kh4[1], kh4[2], kh4[3], smK + boff);
                MMA16816(sacc[nj * 2],     qf, kh4[0], kh4[1]);
                MMA16816(sacc[nj * 2 + 1], qf, kh4[2], kh4[3]);
            }
        }

        // ---- wm load: scale + mask via sign ----
        float wreg[8][4];
        #pragma unroll
        for (int ni = 0; ni < 8; ni++) {
            int s = s0 + ni * 8 + c2;
            float2 w0 = *(const float2*)&wrow0[s];
            float2 w1 = *(const float2*)&wrow1[s];
            wreg[ni][0] = w0.x; wreg[ni][1] = w0.y;
            wreg[ni][2] = w1.x; wreg[ni][3] = w1.y;
            sacc[ni][0] = w0.x > 0.f ? sacc[ni][0] * 0.125f : NEG_;
            sacc[ni][1] = w0.y > 0.f ? sacc[ni][1] * 0.125f : NEG_;
            sacc[ni][2] = w1.x > 0.f ? sacc[ni][2] * 0.125f : NEG_;
            sacc[ni][3] = w1.y > 0.f ? sacc[ni][3] * 0.125f : NEG_;
        }

        // ---- row max ----
        float mx0 = -3.0e38f, mx1 = -3.0e38f;
        #pragma unroll
        for (int ni = 0; ni < 8; ni++) {
            mx0 = fmaxf(mx0, fmaxf(sacc[ni][0], sacc[ni][1]));
            mx1 = fmaxf(mx1, fmaxf(sacc[ni][2], sacc[ni][3]));
        }
        mx0 = fmaxf(mx0, __shfl_xor_sync(0xffffffff, mx0, 1));
        mx0 = fmaxf(mx0, __shfl_xor_sync(0xffffffff, mx0, 2));
        mx1 = fmaxf(mx1, __shfl_xor_sync(0xffffffff, mx1, 1));
        mx1 = fmaxf(mx1, __shfl_xor_sync(0xffffffff, mx1, 2));

        float mnew0 = fmaxf(mstat0, mx0);
        float mnew1 = fmaxf(mstat1, mx1);
        float fr0 = __expf(mstat0 - mnew0);
        float fr1 = __expf(mstat1 - mnew1);
        mstat0 = mnew0; mstat1 = mnew1;

        // ---- exp + row sum ----
        float sum0 = 0.f, sum1 = 0.f;
        #pragma unroll
        for (int ni = 0; ni < 8; ni++) {
            sacc[ni][0] = __expf(sacc[ni][0] - mnew0);
            sacc[ni][1] = __expf(sacc[ni][1] - mnew0);
            sacc[ni][2] = __expf(sacc[ni][2] - mnew1);
            sacc[ni][3] = __expf(sacc[ni][3] - mnew1);
            sum0 += sacc[ni][0] + sacc[ni][1];
            sum1 += sacc[ni][2] + sacc[ni][3];
        }
        sum0 += __shfl_xor_sync(0xffffffff, sum0, 1);
        sum0 += __shfl_xor_sync(0xffffffff, sum0, 2);
        sum1 += __shfl_xor_sync(0xffffffff, sum1, 1);
        sum1 += __shfl_xor_sync(0xffffffff, sum1, 2);
        lstat0 = lstat0 * fr0 + sum0;
        lstat1 = lstat1 * fr1 + sum1;

        // ---- numerator modulation + pack P fragments (single f16) ----
        uint32_t aP[4][4];
        #pragma unroll
        for (int j = 0; j < 4; j++) {
            #pragma unroll
            for (int half = 0; half < 2; half++) {
                int ni = 2 * j + half;
                float p00 = sacc[ni][0] * wreg[ni][0];
                float p01 = sacc[ni][1] * wreg[ni][1];
                float p10 = sacc[ni][2] * wreg[ni][2];
                float p11 = sacc[ni][3] * wreg[ni][3];
                aP[j][half * 2 + 0] = pack_h2(p00, p01);
                aP[j][half * 2 + 1] = pack_h2(p10, p11);
            }
        }

        // ---- rescale O, then O += P @ V ----
        #pragma unroll
        for (int ni = 0; ni < 8; ni++) {
            oacc[ni][0] *= fr0; oacc[ni][1] *= fr0;
            oacc[ni][2] *= fr1; oacc[ni][3] *= fr1;
        }
        #pragma unroll
        for (int j = 0; j < 4; j++) {
            #pragma unroll
            for (int nj = 0; nj < 4; nj++) {
                uint32_t vh4[4];
                uint32_t boff = ((j * 16 + (lane & 15)) * FSTR +
                                 (nj * 2 + ((lane >> 4) & 1)) * 8) * 2;
                LDSM_X4T(vh4[0], vh4[1], vh4[2], vh4[3], smV + boff);
                MMA16816(oacc[nj * 2],     aP[j], vh4[0], vh4[1]);
                MMA16816(oacc[nj * 2 + 1], aP[j], vh4[2], vh4[3]);
            }
        }
    }

    // ---- epilogue: /l, write single f16 ----
    {
        float inv0 = 1.0f / lstat0;
        float inv1 = 1.0f / lstat1;
        size_t row0 = (size_t)(b * T_ + qr0) * C_ + h * HD_;
        size_t row1 = (size_t)(b * T_ + qr1) * C_ + h * HD_;
        #pragma unroll
        for (int ni = 0; ni < 8; ni++) {
            int c = ni * 8 + c2;
            *(uint32_t*)&O[row0 + c] = pack_h2(oacc[ni][0] * inv0,
                                               oacc[ni][1] * inv0);
            *(uint32_t*)&O[row1 + c] = pack_h2(oacc[ni][2] * inv1,
                                               oacc[ni][3] * inv1);
        }
    }
}

// ============================================================================
// Launch
// ============================================================================
extern "C" void kernel_launch(void* const* d_in, const int* in_sizes, int n_in,
                              void* d_out, int out_size)
{
    const float* x_q  = (const float*)d_in[0];
    const float* x_r  = (const float*)d_in[1];
    const float* y    = (const float*)d_in[2];
    const int*   mask = (const int*)  d_in[3];
    const float* dist = (const float*)d_in[4];
    const float* Wq   = (const float*)d_in[5];
    const float* bq   = (const float*)d_in[6];
    const float* Wk   = (const float*)d_in[7];
    const float* bk   = (const float*)d_in[8];
    const float* Wv   = (const float*)d_in[9];
    const float* bv   = (const float*)d_in[10];
    const float* Wp   = (const float*)d_in[11];
    const float* bp   = (const float*)d_in[12];
    float* out = (float*)d_out;

    f16 *qb, *kb, *vb, *ob, *xq, *xr, *yb, *wq, *wk, *wv, *wp;
    float* wmp;
    cudaGetSymbolAddress((void**)&qb, g_Q);
    cudaGetSymbolAddress((void**)&kb, g_K);
    cudaGetSymbolAddress((void**)&vb, g_V);
    cudaGetSymbolAddress((void**)&ob, g_O);
    cudaGetSymbolAddress((void**)&xq, g_xq);
    cudaGetSymbolAddress((void**)&xr, g_xr);
    cudaGetSymbolAddress((void**)&yb, g_y);
    cudaGetSymbolAddress((void**)&wq, g_Wq);
    cudaGetSymbolAddress((void**)&wk, g_Wk);
    cudaGetSymbolAddress((void**)&wv, g_Wv);
    cudaGetSymbolAddress((void**)&wp, g_Wp);
    cudaGetSymbolAddress((void**)&wmp, g_wm);

    cudaFuncSetAttribute(gemm_mma_kernel,
                         cudaFuncAttributeMaxDynamicSharedMemorySize, GEMM_SMEM);
    cudaFuncSetAttribute(flash_mma_kernel,
                         cudaFuncAttributeMaxDynamicSharedMemorySize, FLASH_SMEM);

    // ---- quantize all fp32 inputs to single f16 (MLP=4); build wm ----
    const int MC4 = M_ * C_ / 4;          // 1,048,576
    const int CC4 = C_ * C_ / 4;          // 262,144
    quant_kernel<<<MC4 / 1024, 256>>>((const float4*)x_q, (uint2*)xq, MC4);
    quant_kernel<<<MC4 / 1024, 256>>>((const float4*)x_r, (uint2*)xr, MC4);
    quant_kernel<<<NI_ * MC4 / 1024, 256>>>((const float4*)y, (uint2*)yb, NI_ * MC4);
    quant_kernel<<<CC4 / 1024, 256>>>((const float4*)Wq, (uint2*)wq, CC4);
    quant_kernel<<<CC4 / 1024, 256>>>((const float4*)Wk, (uint2*)wk, CC4);
    quant_kernel<<<NI_ * CC4 / 1024, 256>>>((const float4*)Wv, (uint2*)wv, NI_ * CC4);
    quant_kernel<<<CC4 / 1024, 256>>>((const float4*)Wp, (uint2*)wp, CC4);
    {
        const int n4 = B_ * T_ * T_ / 4;  // 2,097,152
        wm_kernel<<<n4 / 1024, 256>>>((const int4*)mask, (const float4*)dist,
                                      (float4*)wmp, n4);
    }

    dim3 gblk(256);
    dim3 ggrd(C_ / 128, M_ / 128);       // (8, 32) = 256 CTAs

    // projections -> single f16
    gemm_mma_kernel<<<ggrd, gblk, GEMM_SMEM>>>(xq, wq, bq, nullptr, qb,
                                               1, 0, 0, 1);
    gemm_mma_kernel<<<ggrd, gblk, GEMM_SMEM>>>(xr, wk, bk, nullptr, kb,
                                               1, 0, 0, 1);
    gemm_mma_kernel<<<ggrd, gblk, GEMM_SMEM>>>(yb, wv, bv, nullptr, vb,
                                               NI_, (size_t)M_ * C_,
                                               (size_t)C_ * C_, 1);

    dim3 fgrd(B_ * H_, T_ / FQ);         // (32, 16)
    flash_mma_kernel<<<fgrd, 256, FLASH_SMEM>>>(qb, kb, vb, wmp, ob);

    // out projection -> fp32
    gemm_mma_kernel<<<ggrd, gblk, GEMM_SMEM>>>(ob, wp, bp, out, nullptr,
                                               1, 0, 0, 0);
}

// round 16
// speedup vs baseline: 1.7230x; 1.1036x over previous
#include <cuda_runtime.h>
#include <cuda_fp16.h>
#include <cstdint>

// Problem shape (fixed by dataset)
#define B_  2
#define T_  2048
#define C_  1024
#define H_  16
#define HD_ 64
#define NI_ 3
#define M_  (B_ * T_)
#define NEG_ (-1e9f)

typedef __half f16;

// -------- scratch (device globals; no allocation allowed) --------
__device__ f16 g_Q[(size_t)M_ * C_];
__device__ f16 g_K[(size_t)M_ * C_];
__device__ f16 g_V[(size_t)M_ * C_];
__device__ f16 g_O[(size_t)M_ * C_];
__device__ f16 g_xq[(size_t)M_ * C_];
__device__ f16 g_xr[(size_t)M_ * C_];
__device__ f16 g_y [(size_t)NI_ * M_ * C_];
__device__ f16 g_Wq[(size_t)C_ * C_];
__device__ f16 g_Wk[(size_t)C_ * C_];
__device__ f16 g_Wv[(size_t)NI_ * C_ * C_];
__device__ f16 g_Wp[(size_t)C_ * C_];
__device__ float g_wm[(size_t)B_ * T_ * T_];  // mask? exp(-4d^2) : -1

// ============================================================================
// helpers
// ============================================================================
__device__ __forceinline__ uint32_t smem_u32(const void* p) {
    uint32_t a;
    asm("{ .reg .u64 t; cvta.to.shared.u64 t, %1; cvt.u32.u64 %0, t; }"
        : "=r"(a) : "l"(p));
    return a;
}
__device__ __forceinline__ uint32_t pack_h2(float a, float b) {
    f16 h0 = __float2half_rn(a);
    f16 h1 = __float2half_rn(b);
    return ((uint32_t)__half_as_ushort(h1) << 16) | __half_as_ushort(h0);
}

#define CP_ASYNC16(dst, src) \
    asm volatile("cp.async.cg.shared.global [%0], [%1], 16;" :: "r"(dst), "l"(src))
#define CP_COMMIT() asm volatile("cp.async.commit_group;" ::: "memory")
#define CP_WAIT(n)  asm volatile("cp.async.wait_group %0;" :: "n"(n) : "memory")

#define LDSM_X4(r0, r1, r2, r3, addr) \
    asm volatile("ldmatrix.sync.aligned.m8n8.x4.shared.b16 {%0,%1,%2,%3}, [%4];" \
                 : "=r"(r0), "=r"(r1), "=r"(r2), "=r"(r3) : "r"(addr))
#define LDSM_X4T(r0, r1, r2, r3, addr) \
    asm volatile("ldmatrix.sync.aligned.m8n8.x4.trans.shared.b16 {%0,%1,%2,%3}, [%4];" \
                 : "=r"(r0), "=r"(r1), "=r"(r2), "=r"(r3) : "r"(addr))

#define MMA16816(d, a, b0, b1) \
    asm volatile("mma.sync.aligned.m16n8k16.row.col.f32.f16.f16.f32 " \
                 "{%0,%1,%2,%3}, {%4,%5,%6,%7}, {%8,%9}, {%0,%1,%2,%3};" \
                 : "+f"((d)[0]), "+f"((d)[1]), "+f"((d)[2]), "+f"((d)[3]) \
                 : "r"((a)[0]), "r"((a)[1]), "r"((a)[2]), "r"((a)[3]), \
                   "r"(b0), "r"(b1))

// ============================================================================
// merged quant kernel: all 7 fp32 -> f16 conversions in one launch.
// Segment boundaries (float4 units) are multiples of 1024 -> each block is
// entirely within one segment.  MLP=4.
// ============================================================================
#define SEG0 (M_ * C_ / 4)                 // xq: 1048576
#define SEG1 (SEG0 + M_ * C_ / 4)          // xr
#define SEG2 (SEG1 + NI_ * M_ * C_ / 4)    // y
#define SEG3 (SEG2 + C_ * C_ / 4)          // Wq
#define SEG4 (SEG3 + C_ * C_ / 4)          // Wk
#define SEG5 (SEG4 + NI_ * C_ * C_ / 4)    // Wv
#define SEG6 (SEG5 + C_ * C_ / 4)          // Wp (total)
#define QBLOCKS (SEG6 / 1024)              // 6656

__global__ __launch_bounds__(256) void quant_all_kernel(
    const float4* __restrict__ xq, const float4* __restrict__ xr,
    const float4* __restrict__ y,  const float4* __restrict__ Wq,
    const float4* __restrict__ Wk, const float4* __restrict__ Wv,
    const float4* __restrict__ Wp,
    uint2* __restrict__ dxq, uint2* __restrict__ dxr, uint2* __restrict__ dy,
    uint2* __restrict__ dWq, uint2* __restrict__ dWk, uint2* __restrict__ dWv,
    uint2* __restrict__ dWp)
{
    int gbase = blockIdx.x * 1024 + threadIdx.x;
    const float4* src;
    uint2* dst;
    int off;
    if      (gbase < SEG0) { src = xq; dst = dxq; off = gbase; }
    else if (gbase < SEG1) { src = xr; dst = dxr; off = gbase - SEG0; }
    else if (gbase < SEG2) { src = y;  dst = dy;  off = gbase - SEG1; }
    else if (gbase < SEG3) { src = Wq; dst = dWq; off = gbase - SEG2; }
    else if (gbase < SEG4) { src = Wk; dst = dWk; off = gbase - SEG3; }
    else if (gbase < SEG5) { src = Wv; dst = dWv; off = gbase - SEG4; }
    else                   { src = Wp; dst = dWp; off = gbase - SEG5; }

    float4 f[4];
    #pragma unroll
    for (int u = 0; u < 4; u++) f[u] = src[off + u * 256];
    #pragma unroll
    for (int u = 0; u < 4; u++)
        dst[off + u * 256] = make_uint2(pack_h2(f[u].x, f[u].y),
                                        pack_h2(f[u].z, f[u].w));
}

// ============================================================================
// wm kernel (MLP=4): wm = mask ? exp(-4 d^2) : -1
// ============================================================================
__global__ __launch_bounds__(256) void wm_kernel(
    const int4* __restrict__ mask, const float4* __restrict__ dist,
    float4* __restrict__ wm, int n4)
{
    int base = blockIdx.x * 1024 + threadIdx.x;
    int4 m[4]; float4 d[4];
    #pragma unroll
    for (int u = 0; u < 4; u++) m[u] = mask[base + u * 256];
    #pragma unroll
    for (int u = 0; u < 4; u++) d[u] = dist[base + u * 256];
    #pragma unroll
    for (int u = 0; u < 4; u++) {
        float4 w;
        w.x = m[u].x ? __expf(-4.0f * d[u].x * d[u].x) : -1.0f;
        w.y = m[u].y ? __expf(-4.0f * d[u].y * d[u].y) : -1.0f;
        w.z = m[u].z ? __expf(-4.0f * d[u].z * d[u].z) : -1.0f;
        w.w = m[u].w ? __expf(-4.0f * d[u].w * d[u].w) : -1.0f;
        wm[base + u * 256] = w;
    }
}

// ============================================================================
// fp16 single-mma GEMM body (shared by out-proj kernel and merged QKV kernel)
// 3-stage pipeline, 2 CTAs/SM, 128x128 CTA tile, 8 warps (2m x 4n).
// ============================================================================
#define ASTR 72
#define WSTR 136
#define BKC  64
#define A_BYTES (128 * ASTR * 2)                   // 18432
#define W_BYTES (64 * WSTR * 2)                    // 17408
#define BUF_BYTES (A_BYTES + W_BYTES)              // 35840
#define SMB_BUF 1024
#define GEMM_SMEM (SMB_BUF + 3 * BUF_BYTES)        // 108544 -> 2 CTAs/SM

__device__ __forceinline__ void load_chunk(
    uint32_t sbuf, const f16* __restrict__ A, const f16* __restrict__ W,
    int bm, int bn, int k0, int tid)
{
    #pragma unroll
    for (int v = 0; v < 4; v++) {
        int idx = tid + v * 256;
        int r = idx >> 3, c = idx & 7;
        size_t go = (size_t)(bm + r) * C_ + k0 + c * 8;
        uint32_t so = sbuf + r * (ASTR * 2) + c * 16;
        CP_ASYNC16(so, A + go);
    }
    #pragma unroll
    for (int v = 0; v < 4; v++) {
        int idx = tid + v * 256;
        int r = idx >> 4, c = idx & 15;
        size_t go = (size_t)(k0 + r) * C_ + bn + c * 8;
        uint32_t so = sbuf + A_BYTES + r * (WSTR * 2) + c * 16;
        CP_ASYNC16(so, W + go);
    }
}

__device__ __forceinline__ void compute_chunk(
    uint32_t sbuf, int wm_, int wn, int lane, float acc[4][4][4])
{
    const uint32_t smA = sbuf;
    const uint32_t smW = sbuf + A_BYTES;
    const int m0 = wm_ * 64, n0 = wn * 32;
    const int ar = lane & 15;
    const int ac = (lane >> 4) << 3;

    #pragma unroll
    for (int ks = 0; ks < 4; ks++) {
        const int kk = ks * 16;
        uint32_t ah[4][4], bh[2][4];
        #pragma unroll
        for (int mi = 0; mi < 4; mi++) {
            uint32_t off = ((m0 + mi * 16 + ar) * ASTR + kk + ac) * 2;
            LDSM_X4(ah[mi][0], ah[mi][1], ah[mi][2], ah[mi][3], smA + off);
        }
        #pragma unroll
        for (int nj = 0; nj < 2; nj++) {
            uint32_t off = ((kk + ar) * WSTR + n0 + nj * 16 +
                            ((lane >> 4) & 1) * 8) * 2;
            LDSM_X4T(bh[nj][0], bh[nj][1], bh[nj][2], bh[nj][3], smW + off);
        }
        #pragma unroll
        for (int mi = 0; mi < 4; mi++)
            #pragma unroll
            for (int nj = 0; nj < 2; nj++) {
                MMA16816(acc[mi][nj * 2],     ah[mi], bh[nj][0], bh[nj][1]);
                MMA16816(acc[mi][nj * 2 + 1], ah[mi], bh[nj][2], bh[nj][3]);
            }
    }
}

__device__ __forceinline__ void gemm_body(
    char* smc, const f16* __restrict__ A, const f16* __restrict__ W,
    const float* __restrict__ bias, float* __restrict__ C,
    f16* __restrict__ Chi, int nmat, size_t strideA, size_t strideW,
    int outmode, int bm, int bn)
{
    const uint32_t smb = smem_u32(smc);
    float* s_bias = (float*)smc;

    const int tid = threadIdx.x;
    const int lane = tid & 31;
    const int wid = tid >> 5;
    const int wm_ = wid & 1;
    const int wn = wid >> 1;

    if (tid < 128) {
        float bs = 0.f;
        for (int n = 0; n < nmat; n++) bs += bias[(size_t)n * C_ + bn + tid];
        s_bias[tid] = bs;
    }

    float acc[4][4][4];
    #pragma unroll
    for (int mi = 0; mi < 4; mi++)
        #pragma unroll
        for (int ni = 0; ni < 4; ni++)
            #pragma unroll
            for (int r = 0; r < 4; r++) acc[mi][ni][r] = 0.f;

    const int NC = nmat * (C_ / BKC);

    load_chunk(smb + SMB_BUF, A, W, bm, bn, 0, tid);
    CP_COMMIT();
    load_chunk(smb + SMB_BUF + BUF_BYTES, A, W, bm, bn, BKC, tid);
    CP_COMMIT();

    for (int c = 0; c < NC; c++) {
        if (c + 1 < NC) { CP_WAIT(1); } else { CP_WAIT(0); }
        __syncthreads();
        if (c + 2 < NC) {
            int cc = c + 2;
            int nm = cc >> 4;
            int k0 = (cc & 15) * BKC;
            load_chunk(smb + SMB_BUF + (cc % 3) * BUF_BYTES,
                       A + (size_t)nm * strideA,
                       W + (size_t)nm * strideW, bm, bn, k0, tid);
            CP_COMMIT();
        }
        compute_chunk(smb + SMB_BUF + (c % 3) * BUF_BYTES, wm_, wn, lane, acc);
    }

    const int r0 = bm + wm_ * 64 + (lane >> 2);
    const int c0rel = wn * 32 + 2 * (lane & 3);
    #pragma unroll
    for (int mi = 0; mi < 4; mi++) {
        #pragma unroll
        for (int ni = 0; ni < 4; ni++) {
            int crel = c0rel + ni * 8;
            float b0 = s_bias[crel], b1 = s_bias[crel + 1];
            int row = r0 + mi * 16;
            float a0 = acc[mi][ni][0] + b0, a1 = acc[mi][ni][1] + b1;
            float a2 = acc[mi][ni][2] + b0, a3 = acc[mi][ni][3] + b1;
            if (outmode == 0) {
                *(float2*)&C[(size_t)row * C_ + bn + crel] = make_float2(a0, a1);
                *(float2*)&C[(size_t)(row + 8) * C_ + bn + crel] = make_float2(a2, a3);
            } else {
                *(uint32_t*)&Chi[(size_t)row * C_ + bn + crel] = pack_h2(a0, a1);
                *(uint32_t*)&Chi[(size_t)(row + 8) * C_ + bn + crel] = pack_h2(a2, a3);
            }
        }
    }
}

// out-projection (single GEMM, fp32 out)
__global__ __launch_bounds__(256, 2) void gemm_mma_kernel(
    const f16* __restrict__ A, const f16* __restrict__ W,
    const float* __restrict__ bias, float* __restrict__ C)
{
    extern __shared__ char smc[];
    gemm_body(smc, A, W, bias, C, nullptr, 1, 0, 0, 0,
              blockIdx.y * 128, blockIdx.x * 128);
}

// merged Q/K/V projections: z=0 -> V (nmat=3, longest, scheduled first),
// z=1 -> Q, z=2 -> K.  All write f16.
__global__ __launch_bounds__(256, 2) void gemm_qkv_kernel(
    const f16* __restrict__ xq, const f16* __restrict__ Wq,
    const float* __restrict__ bq, f16* __restrict__ Qo,
    const f16* __restrict__ xr, const f16* __restrict__ Wk,
    const float* __restrict__ bk, f16* __restrict__ Ko,
    const f16* __restrict__ y,  const f16* __restrict__ Wv,
    const float* __restrict__ bv, f16* __restrict__ Vo)
{
    extern __shared__ char smc[];
    const int bm = blockIdx.y * 128;
    const int bn = blockIdx.x * 128;
    if (blockIdx.z == 0) {
        gemm_body(smc, y, Wv, bv, nullptr, Vo, NI_,
                  (size_t)M_ * C_, (size_t)C_ * C_, 1, bm, bn);
    } else if (blockIdx.z == 1) {
        gemm_body(smc, xq, Wq, bq, nullptr, Qo, 1, 0, 0, 1, bm, bn);
    } else {
        gemm_body(smc, xr, Wk, bk, nullptr, Ko, 1, 0, 0, 1, bm, bn);
    }
}

// ============================================================================
// Flash attention: single-fp16 mma, register softmax, precomputed wm,
// 3-stage KV pipeline, 2 CTAs/SM. 128 q-rows, kv chunks of 64, 8 warps.
// ============================================================================
#define FQ 128
#define FS 64
#define FSTR 72
#define OFF_Q 0
#define OFF_BUF 18432
#define KV_BUF_BYTES 18432                         // K 9216 + V 9216
#define FLASH_SMEM (OFF_BUF + 3 * KV_BUF_BYTES)    // 73728 -> 2 CTAs/SM

__device__ __forceinline__ void flash_load_kv(
    uint32_t bb, const f16* __restrict__ K, const f16* __restrict__ V,
    int b, int h, int s0, int tid)
{
    #pragma unroll
    for (int v = 0; v < 2; v++) {
        int idx = tid + v * 256;
        int r = idx >> 3, c = idx & 7;
        size_t go = (size_t)(b * T_ + s0 + r) * C_ + h * HD_ + c * 8;
        uint32_t so = bb + r * (FSTR * 2) + c * 16;
        CP_ASYNC16(so,        K + go);
        CP_ASYNC16(so + 9216, V + go);
    }
}

__global__ __launch_bounds__(256, 2) void flash_mma_kernel(
    const f16* __restrict__ Q, const f16* __restrict__ K,
    const f16* __restrict__ V, const float* __restrict__ wm,
    f16* __restrict__ O)
{
    extern __shared__ char smc[];
    const uint32_t smb = smem_u32(smc);

    const int bh  = blockIdx.x;
    const int b   = bh >> 4;
    const int h   = bh & 15;
    const int t10 = blockIdx.y * FQ;
    const int tid = threadIdx.x;
    const int lane = tid & 31;
    const int wid = tid >> 5;
    const int m0 = wid * 16;
    const int g  = lane >> 2;
    const int c2 = (lane & 3) * 2;

    const int qr0 = t10 + m0 + g;
    const int qr1 = qr0 + 8;
    const float* wrow0 = &wm[(size_t)(b * T_ + qr0) * T_];
    const float* wrow1 = &wm[(size_t)(b * T_ + qr1) * T_];

    // ---- load Q tile (single f16) ----
    #pragma unroll
    for (int v = 0; v < 4; v++) {
        int idx = tid + v * 256;
        int r = idx >> 3, c = idx & 7;
        size_t go = (size_t)(b * T_ + t10 + r) * C_ + h * HD_ + c * 8;
        uint32_t so = smb + OFF_Q + r * (FSTR * 2) + c * 16;
        CP_ASYNC16(so, Q + go);
    }
    CP_COMMIT();
    // ---- kv chunks 0, 1 ----
    flash_load_kv(smb + OFF_BUF, K, V, b, h, 0, tid);
    CP_COMMIT();
    flash_load_kv(smb + OFF_BUF + KV_BUF_BYTES, K, V, b, h, FS, tid);
    CP_COMMIT();

    float mstat0 = -3.0e38f, mstat1 = -3.0e38f;
    float lstat0 = 0.f, lstat1 = 0.f;

    float oacc[8][4];
    #pragma unroll
    for (int ni = 0; ni < 8; ni++)
        #pragma unroll
        for (int r = 0; r < 4; r++) oacc[ni][r] = 0.f;

    const int NITER = T_ / FS;           // 32

    for (int it = 0; it < NITER; it++) {
        if (it + 1 < NITER) { CP_WAIT(1); } else { CP_WAIT(0); }
        __syncthreads();
        if (it + 2 < NITER) {
            flash_load_kv(smb + OFF_BUF + ((it + 2) % 3) * KV_BUF_BYTES,
                          K, V, b, h, (it + 2) * FS, tid);
            CP_COMMIT();
        }

        const int s0 = it * FS;
        const uint32_t bb = smb + OFF_BUF + (it % 3) * KV_BUF_BYTES;
        const uint32_t smK = bb;
        const uint32_t smV = bb + 9216;

        // ---- S = Q K^T ----
        float sacc[8][4];
        #pragma unroll
        for (int ni = 0; ni < 8; ni++)
            #pragma unroll
            for (int r = 0; r < 4; r++) sacc[ni][r] = 0.f;

        #pragma unroll
        for (int ks = 0; ks < 4; ks++) {
            const int k0 = ks * 16;
            uint32_t qf[4];
            uint32_t aoff = (uint32_t)OFF_Q +
                ((m0 + (lane & 15)) * FSTR + k0 + ((lane >> 4) << 3)) * 2;
            LDSM_X4(qf[0], qf[1], qf[2], qf[3], smb + aoff);
            #pragma unroll
            for (int nj = 0; nj < 4; nj++) {
                uint32_t kh4[4];
                uint32_t boff = ((nj * 16 + (lane & 7) + ((lane >> 4) << 3)) * FSTR +
                                 k0 + ((lane >> 3) & 1) * 8) * 2;
                LDSM_X4(kh4[0], kh4[1], kh4[2], kh4[3], smK + boff);
                MMA16816(sacc[nj * 2],     qf, kh4[0], kh4[1]);
                MMA16816(sacc[nj * 2 + 1], qf, kh4[2], kh4[3]);
            }
        }

        // ---- wm load: scale + mask via sign ----
        float wreg[8][4];
        #pragma unroll
        for (int ni = 0; ni < 8; ni++) {
            int s = s0 + ni * 8 + c2;
            float2 w0 = *(const float2*)&wrow0[s];
            float2 w1 = *(const float2*)&wrow1[s];
            wreg[ni][0] = w0.x; wreg[ni][1] = w0.y;
            wreg[ni][2] = w1.x; wreg[ni][3] = w1.y;
            sacc[ni][0] = w0.x > 0.f ? sacc[ni][0] * 0.125f : NEG_;
            sacc[ni][1] = w0.y > 0.f ? sacc[ni][1] * 0.125f : NEG_;
            sacc[ni][2] = w1.x > 0.f ? sacc[ni][2] * 0.125f : NEG_;
            sacc[ni][3] = w1.y > 0.f ? sacc[ni][3] * 0.125f : NEG_;
        }

        // ---- row max ----
        float mx0 = -3.0e38f, mx1 = -3.0e38f;
        #pragma unroll
        for (int ni = 0; ni < 8; ni++) {
            mx0 = fmaxf(mx0, fmaxf(sacc[ni][0], sacc[ni][1]));
            mx1 = fmaxf(mx1, fmaxf(sacc[ni][2], sacc[ni][3]));
        }
        mx0 = fmaxf(mx0, __shfl_xor_sync(0xffffffff, mx0, 1));
        mx0 = fmaxf(mx0, __shfl_xor_sync(0xffffffff, mx0, 2));
        mx1 = fmaxf(mx1, __shfl_xor_sync(0xffffffff, mx1, 1));
        mx1 = fmaxf(mx1, __shfl_xor_sync(0xffffffff, mx1, 2));

        float mnew0 = fmaxf(mstat0, mx0);
        float mnew1 = fmaxf(mstat1, mx1);
        float fr0 = __expf(mstat0 - mnew0);
        float fr1 = __expf(mstat1 - mnew1);
        mstat0 = mnew0; mstat1 = mnew1;

        // ---- exp + row sum ----
        float sum0 = 0.f, sum1 = 0.f;
        #pragma unroll
        for (int ni = 0; ni < 8; ni++) {
            sacc[ni][0] = __expf(sacc[ni][0] - mnew0);
            sacc[ni][1] = __expf(sacc[ni][1] - mnew0);
            sacc[ni][2] = __expf(sacc[ni][2] - mnew1);
            sacc[ni][3] = __expf(sacc[ni][3] - mnew1);
            sum0 += sacc[ni][0] + sacc[ni][1];
            sum1 += sacc[ni][2] + sacc[ni][3];
        }
        sum0 += __shfl_xor_sync(0xffffffff, sum0, 1);
        sum0 += __shfl_xor_sync(0xffffffff, sum0, 2);
        sum1 += __shfl_xor_sync(0xffffffff, sum1, 1);
        sum1 += __shfl_xor_sync(0xffffffff, sum1, 2);
        lstat0 = lstat0 * fr0 + sum0;
        lstat1 = lstat1 * fr1 + sum1;

        // ---- numerator modulation + pack P fragments (single f16) ----
        uint32_t aP[4][4];
        #pragma unroll
        for (int j = 0; j < 4; j++) {
            #pragma unroll
            for (int half = 0; half < 2; half++) {
                int ni = 2 * j + half;
                float p00 = sacc[ni][0] * wreg[ni][0];
                float p01 = sacc[ni][1] * wreg[ni][1];
                float p10 = sacc[ni][2] * wreg[ni][2];
                float p11 = sacc[ni][3] * wreg[ni][3];
                aP[j][half * 2 + 0] = pack_h2(p00, p01);
                aP[j][half * 2 + 1] = pack_h2(p10, p11);
            }
        }

        // ---- rescale O, then O += P @ V ----
        #pragma unroll
        for (int ni = 0; ni < 8; ni++) {
            oacc[ni][0] *= fr0; oacc[ni][1] *= fr0;
            oacc[ni][2] *= fr1; oacc[ni][3] *= fr1;
        }
        #pragma unroll
        for (int j = 0; j < 4; j++) {
            #pragma unroll
            for (int nj = 0; nj < 4; nj++) {
                uint32_t vh4[4];
                uint32_t boff = ((j * 16 + (lane & 15)) * FSTR +
                                 (nj * 2 + ((lane >> 4) & 1)) * 8) * 2;
                LDSM_X4T(vh4[0], vh4[1], vh4[2], vh4[3], smV + boff);
                MMA16816(oacc[nj * 2],     aP[j], vh4[0], vh4[1]);
                MMA16816(oacc[nj * 2 + 1], aP[j], vh4[2], vh4[3]);
            }
        }
    }

    // ---- epilogue: /l, write single f16 ----
    {
        float inv0 = 1.0f / lstat0;
        float inv1 = 1.0f / lstat1;
        size_t row0 = (size_t)(b * T_ + qr0) * C_ + h * HD_;
        size_t row1 = (size_t)(b * T_ + qr1) * C_ + h * HD_;
        #pragma unroll
        for (int ni = 0; ni < 8; ni++) {
            int c = ni * 8 + c2;
            *(uint32_t*)&O[row0 + c] = pack_h2(oacc[ni][0] * inv0,
                                               oacc[ni][1] * inv0);
            *(uint32_t*)&O[row1 + c] = pack_h2(oacc[ni][2] * inv1,
                                               oacc[ni][3] * inv1);
        }
    }
}

// ============================================================================
// Launch
// ============================================================================
extern "C" void kernel_launch(void* const* d_in, const int* in_sizes, int n_in,
                              void* d_out, int out_size)
{
    const float* x_q  = (const float*)d_in[0];
    const float* x_r  = (const float*)d_in[1];
    const float* y    = (const float*)d_in[2];
    const int*   mask = (const int*)  d_in[3];
    const float* dist = (const float*)d_in[4];
    const float* Wq   = (const float*)d_in[5];
    const float* bq   = (const float*)d_in[6];
    const float* Wk   = (const float*)d_in[7];
    const float* bk   = (const float*)d_in[8];
    const float* Wv   = (const float*)d_in[9];
    const float* bv   = (const float*)d_in[10];
    const float* Wp   = (const float*)d_in[11];
    const float* bp   = (const float*)d_in[12];
    float* out = (float*)d_out;

    f16 *qb, *kb, *vb, *ob, *xq, *xr, *yb, *wq, *wk, *wv, *wp;
    float* wmp;
    cudaGetSymbolAddress((void**)&qb, g_Q);
    cudaGetSymbolAddress((void**)&kb, g_K);
    cudaGetSymbolAddress((void**)&vb, g_V);
    cudaGetSymbolAddress((void**)&ob, g_O);
    cudaGetSymbolAddress((void**)&xq, g_xq);
    cudaGetSymbolAddress((void**)&xr, g_xr);
    cudaGetSymbolAddress((void**)&yb, g_y);
    cudaGetSymbolAddress((void**)&wq, g_Wq);
    cudaGetSymbolAddress((void**)&wk, g_Wk);
    cudaGetSymbolAddress((void**)&wv, g_Wv);
    cudaGetSymbolAddress((void**)&wp, g_Wp);
    cudaGetSymbolAddress((void**)&wmp, g_wm);

    cudaFuncSetAttribute(gemm_mma_kernel,
                         cudaFuncAttributeMaxDynamicSharedMemorySize, GEMM_SMEM);
    cudaFuncSetAttribute(gemm_qkv_kernel,
                         cudaFuncAttributeMaxDynamicSharedMemorySize, GEMM_SMEM);
    cudaFuncSetAttribute(flash_mma_kernel,
                         cudaFuncAttributeMaxDynamicSharedMemorySize, FLASH_SMEM);

    // ---- one merged quant launch + wm ----
    quant_all_kernel<<<QBLOCKS, 256>>>(
        (const float4*)x_q, (const float4*)x_r, (const float4*)y,
        (const float4*)Wq, (const float4*)Wk, (const float4*)Wv,
        (const float4*)Wp,
        (uint2*)xq, (uint2*)xr, (uint2*)yb,
        (uint2*)wq, (uint2*)wk, (uint2*)wv, (uint2*)wp);
    {
        const int n4 = B_ * T_ * T_ / 4;  // 2,097,152
        wm_kernel<<<n4 / 1024, 256>>>((const int4*)mask, (const float4*)dist,
                                      (float4*)wmp, n4);
    }

    // ---- merged Q/K/V projections (V first via z=0) ----
    dim3 gblk(256);
    dim3 gqkv(C_ / 128, M_ / 128, 3);    // (8, 32, 3) = 768 CTAs
    gemm_qkv_kernel<<<gqkv, gblk, GEMM_SMEM>>>(xq, wq, bq, qb,
                                               xr, wk, bk, kb,
                                               yb, wv, bv, vb);

    // ---- flash attention ----
    dim3 fgrd(B_ * H_, T_ / FQ);         // (32, 16)
    flash_mma_kernel<<<fgrd, 256, FLASH_SMEM>>>(qb, kb, vb, wmp, ob);

    // ---- out projection -> fp32 ----
    dim3 ggrd(C_ / 128, M_ / 128);       // (8, 32)
    gemm_mma_kernel<<<ggrd, gblk, GEMM_SMEM>>>(ob, wp, bp, out);
}

// round 17
// speedup vs baseline: 1.7558x; 1.0191x over previous
#include <cuda_runtime.h>
#include <cuda_fp16.h>
#include <cstdint>

// Problem shape (fixed by dataset)
#define B_  2
#define T_  2048
#define C_  1024
#define H_  16
#define HD_ 64
#define NI_ 3
#define M_  (B_ * T_)
#define NEG_ (-1e9f)

typedef __half f16;

// -------- scratch (device globals; no allocation allowed) --------
__device__ f16 g_Q[(size_t)M_ * C_];
__device__ f16 g_K[(size_t)M_ * C_];
__device__ f16 g_V[(size_t)M_ * C_];
__device__ f16 g_O[(size_t)M_ * C_];
__device__ f16 g_xq[(size_t)M_ * C_];
__device__ f16 g_xr[(size_t)M_ * C_];
__device__ f16 g_y [(size_t)NI_ * M_ * C_];
__device__ f16 g_Wq[(size_t)C_ * C_];
__device__ f16 g_Wk[(size_t)C_ * C_];
__device__ f16 g_Wv[(size_t)NI_ * C_ * C_];
__device__ f16 g_Wp[(size_t)C_ * C_];
__device__ float g_wm[(size_t)B_ * T_ * T_];  // mask? exp(-4d^2) : -1

// ============================================================================
// helpers
// ============================================================================
__device__ __forceinline__ uint32_t smem_u32(const void* p) {
    uint32_t a;
    asm("{ .reg .u64 t; cvta.to.shared.u64 t, %1; cvt.u32.u64 %0, t; }"
        : "=r"(a) : "l"(p));
    return a;
}
// pack two fp32 -> f16x2 in ONE cvt (lo = a, hi = b); rounding identical to
// two separate cvt.rn.f16.f32.
__device__ __forceinline__ uint32_t pack_h2(float a, float b) {
    uint32_t r;
    asm("cvt.rn.f16x2.f32 %0, %2, %1;" : "=r"(r) : "f"(a), "f"(b));
    return r;
}

#define CP_ASYNC16(dst, src) \
    asm volatile("cp.async.cg.shared.global [%0], [%1], 16;" :: "r"(dst), "l"(src))
#define CP_COMMIT() asm volatile("cp.async.commit_group;" ::: "memory")
#define CP_WAIT(n)  asm volatile("cp.async.wait_group %0;" :: "n"(n) : "memory")

#define LDSM_X4(r0, r1, r2, r3, addr) \
    asm volatile("ldmatrix.sync.aligned.m8n8.x4.shared.b16 {%0,%1,%2,%3}, [%4];" \
                 : "=r"(r0), "=r"(r1), "=r"(r2), "=r"(r3) : "r"(addr))
#define LDSM_X4T(r0, r1, r2, r3, addr) \
    asm volatile("ldmatrix.sync.aligned.m8n8.x4.trans.shared.b16 {%0,%1,%2,%3}, [%4];" \
                 : "=r"(r0), "=r"(r1), "=r"(r2), "=r"(r3) : "r"(addr))

#define MMA16816(d, a, b0, b1) \
    asm volatile("mma.sync.aligned.m16n8k16.row.col.f32.f16.f16.f32 " \
                 "{%0,%1,%2,%3}, {%4,%5,%6,%7}, {%8,%9}, {%0,%1,%2,%3};" \
                 : "+f"((d)[0]), "+f"((d)[1]), "+f"((d)[2]), "+f"((d)[3]) \
                 : "r"((a)[0]), "r"((a)[1]), "r"((a)[2]), "r"((a)[3]), \
                   "r"(b0), "r"(b1))

// ============================================================================
// merged quant kernel: all 7 fp32 -> f16 conversions in one launch (MLP=4).
// ============================================================================
#define SEG0 (M_ * C_ / 4)
#define SEG1 (SEG0 + M_ * C_ / 4)
#define SEG2 (SEG1 + NI_ * M_ * C_ / 4)
#define SEG3 (SEG2 + C_ * C_ / 4)
#define SEG4 (SEG3 + C_ * C_ / 4)
#define SEG5 (SEG4 + NI_ * C_ * C_ / 4)
#define SEG6 (SEG5 + C_ * C_ / 4)
#define QBLOCKS (SEG6 / 1024)

__global__ __launch_bounds__(256) void quant_all_kernel(
    const float4* __restrict__ xq, const float4* __restrict__ xr,
    const float4* __restrict__ y,  const float4* __restrict__ Wq,
    const float4* __restrict__ Wk, const float4* __restrict__ Wv,
    const float4* __restrict__ Wp,
    uint2* __restrict__ dxq, uint2* __restrict__ dxr, uint2* __restrict__ dy,
    uint2* __restrict__ dWq, uint2* __restrict__ dWk, uint2* __restrict__ dWv,
    uint2* __restrict__ dWp)
{
    int gbase = blockIdx.x * 1024 + threadIdx.x;
    const float4* src;
    uint2* dst;
    int off;
    if      (gbase < SEG0) { src = xq; dst = dxq; off = gbase; }
    else if (gbase < SEG1) { src = xr; dst = dxr; off = gbase - SEG0; }
    else if (gbase < SEG2) { src = y;  dst = dy;  off = gbase - SEG1; }
    else if (gbase < SEG3) { src = Wq; dst = dWq; off = gbase - SEG2; }
    else if (gbase < SEG4) { src = Wk; dst = dWk; off = gbase - SEG3; }
    else if (gbase < SEG5) { src = Wv; dst = dWv; off = gbase - SEG4; }
    else                   { src = Wp; dst = dWp; off = gbase - SEG5; }

    float4 f[4];
    #pragma unroll
    for (int u = 0; u < 4; u++) f[u] = src[off + u * 256];
    #pragma unroll
    for (int u = 0; u < 4; u++)
        dst[off + u * 256] = make_uint2(pack_h2(f[u].x, f[u].y),
                                        pack_h2(f[u].z, f[u].w));
}

// ============================================================================
// wm kernel (MLP=4): wm = mask ? exp(-4 d^2) : -1
// ============================================================================
__global__ __launch_bounds__(256) void wm_kernel(
    const int4* __restrict__ mask, const float4* __restrict__ dist,
    float4* __restrict__ wm, int n4)
{
    int base = blockIdx.x * 1024 + threadIdx.x;
    int4 m[4]; float4 d[4];
    #pragma unroll
    for (int u = 0; u < 4; u++) m[u] = mask[base + u * 256];
    #pragma unroll
    for (int u = 0; u < 4; u++) d[u] = dist[base + u * 256];
    #pragma unroll
    for (int u = 0; u < 4; u++) {
        float4 w;
        w.x = m[u].x ? __expf(-4.0f * d[u].x * d[u].x) : -1.0f;
        w.y = m[u].y ? __expf(-4.0f * d[u].y * d[u].y) : -1.0f;
        w.z = m[u].z ? __expf(-4.0f * d[u].z * d[u].z) : -1.0f;
        w.w = m[u].w ? __expf(-4.0f * d[u].w * d[u].w) : -1.0f;
        wm[base + u * 256] = w;
    }
}

// ============================================================================
// fp16 single-mma GEMM body. 3-stage pipeline, 2 CTAs/SM, 128x128 tile.
// outscale multiplies outputs before f16 pack (used to fold 1/sqrt(hd) into Q).
// ============================================================================
#define ASTR 72
#define WSTR 136
#define BKC  64
#define A_BYTES (128 * ASTR * 2)
#define W_BYTES (64 * WSTR * 2)
#define BUF_BYTES (A_BYTES + W_BYTES)
#define SMB_BUF 1024
#define GEMM_SMEM (SMB_BUF + 3 * BUF_BYTES)

__device__ __forceinline__ void load_chunk(
    uint32_t sbuf, const f16* __restrict__ A, const f16* __restrict__ W,
    int bm, int bn, int k0, int tid)
{
    #pragma unroll
    for (int v = 0; v < 4; v++) {
        int idx = tid + v * 256;
        int r = idx >> 3, c = idx & 7;
        size_t go = (size_t)(bm + r) * C_ + k0 + c * 8;
        uint32_t so = sbuf + r * (ASTR * 2) + c * 16;
        CP_ASYNC16(so, A + go);
    }
    #pragma unroll
    for (int v = 0; v < 4; v++) {
        int idx = tid + v * 256;
        int r = idx >> 4, c = idx & 15;
        size_t go = (size_t)(k0 + r) * C_ + bn + c * 8;
        uint32_t so = sbuf + A_BYTES + r * (WSTR * 2) + c * 16;
        CP_ASYNC16(so, W + go);
    }
}

__device__ __forceinline__ void compute_chunk(
    uint32_t sbuf, int wm_, int wn, int lane, float acc[4][4][4])
{
    const uint32_t smA = sbuf;
    const uint32_t smW = sbuf + A_BYTES;
    const int m0 = wm_ * 64, n0 = wn * 32;
    const int ar = lane & 15;
    const int ac = (lane >> 4) << 3;

    #pragma unroll
    for (int ks = 0; ks < 4; ks++) {
        const int kk = ks * 16;
        uint32_t ah[4][4], bh[2][4];
        #pragma unroll
        for (int mi = 0; mi < 4; mi++) {
            uint32_t off = ((m0 + mi * 16 + ar) * ASTR + kk + ac) * 2;
            LDSM_X4(ah[mi][0], ah[mi][1], ah[mi][2], ah[mi][3], smA + off);
        }
        #pragma unroll
        for (int nj = 0; nj < 2; nj++) {
            uint32_t off = ((kk + ar) * WSTR + n0 + nj * 16 +
                            ((lane >> 4) & 1) * 8) * 2;
            LDSM_X4T(bh[nj][0], bh[nj][1], bh[nj][2], bh[nj][3], smW + off);
        }
        #pragma unroll
        for (int mi = 0; mi < 4; mi++)
            #pragma unroll
            for (int nj = 0; nj < 2; nj++) {
                MMA16816(acc[mi][nj * 2],     ah[mi], bh[nj][0], bh[nj][1]);
                MMA16816(acc[mi][nj * 2 + 1], ah[mi], bh[nj][2], bh[nj][3]);
            }
    }
}

__device__ __forceinline__ void gemm_body(
    char* smc, const f16* __restrict__ A, const f16* __restrict__ W,
    const float* __restrict__ bias, float* __restrict__ C,
    f16* __restrict__ Chi, int nmat, size_t strideA, size_t strideW,
    int outmode, float outscale, int bm, int bn)
{
    const uint32_t smb = smem_u32(smc);
    float* s_bias = (float*)smc;

    const int tid = threadIdx.x;
    const int lane = tid & 31;
    const int wid = tid >> 5;
    const int wm_ = wid & 1;
    const int wn = wid >> 1;

    if (tid < 128) {
        float bs = 0.f;
        for (int n = 0; n < nmat; n++) bs += bias[(size_t)n * C_ + bn + tid];
        s_bias[tid] = bs;
    }

    float acc[4][4][4];
    #pragma unroll
    for (int mi = 0; mi < 4; mi++)
        #pragma unroll
        for (int ni = 0; ni < 4; ni++)
            #pragma unroll
            for (int r = 0; r < 4; r++) acc[mi][ni][r] = 0.f;

    const int NC = nmat * (C_ / BKC);

    load_chunk(smb + SMB_BUF, A, W, bm, bn, 0, tid);
    CP_COMMIT();
    load_chunk(smb + SMB_BUF + BUF_BYTES, A, W, bm, bn, BKC, tid);
    CP_COMMIT();

    for (int c = 0; c < NC; c++) {
        if (c + 1 < NC) { CP_WAIT(1); } else { CP_WAIT(0); }
        __syncthreads();
        if (c + 2 < NC) {
            int cc = c + 2;
            int nm = cc >> 4;
            int k0 = (cc & 15) * BKC;
            load_chunk(smb + SMB_BUF + (cc % 3) * BUF_BYTES,
                       A + (size_t)nm * strideA,
                       W + (size_t)nm * strideW, bm, bn, k0, tid);
            CP_COMMIT();
        }
        compute_chunk(smb + SMB_BUF + (c % 3) * BUF_BYTES, wm_, wn, lane, acc);
    }

    const int r0 = bm + wm_ * 64 + (lane >> 2);
    const int c0rel = wn * 32 + 2 * (lane & 3);
    #pragma unroll
    for (int mi = 0; mi < 4; mi++) {
        #pragma unroll
        for (int ni = 0; ni < 4; ni++) {
            int crel = c0rel + ni * 8;
            float b0 = s_bias[crel], b1 = s_bias[crel + 1];
            int row = r0 + mi * 16;
            float a0 = acc[mi][ni][0] + b0, a1 = acc[mi][ni][1] + b1;
            float a2 = acc[mi][ni][2] + b0, a3 = acc[mi][ni][3] + b1;
            if (outmode == 0) {
                *(float2*)&C[(size_t)row * C_ + bn + crel] = make_float2(a0, a1);
                *(float2*)&C[(size_t)(row + 8) * C_ + bn + crel] = make_float2(a2, a3);
            } else {
                a0 *= outscale; a1 *= outscale;
                a2 *= outscale; a3 *= outscale;
                *(uint32_t*)&Chi[(size_t)row * C_ + bn + crel] = pack_h2(a0, a1);
                *(uint32_t*)&Chi[(size_t)(row + 8) * C_ + bn + crel] = pack_h2(a2, a3);
            }
        }
    }
}

// out-projection (single GEMM, fp32 out)
__global__ __launch_bounds__(256, 2) void gemm_mma_kernel(
    const f16* __restrict__ A, const f16* __restrict__ W,
    const float* __restrict__ bias, float* __restrict__ C)
{
    extern __shared__ char smc[];
    gemm_body(smc, A, W, bias, C, nullptr, 1, 0, 0, 0, 1.0f,
              blockIdx.y * 128, blockIdx.x * 128);
}

// merged Q/K/V projections: z=0 -> V (nmat=3, longest, first), z=1 -> Q
// (scaled by 1/sqrt(hd)), z=2 -> K.
__global__ __launch_bounds__(256, 2) void gemm_qkv_kernel(
    const f16* __restrict__ xq, const f16* __restrict__ Wq,
    const float* __restrict__ bq, f16* __restrict__ Qo,
    const f16* __restrict__ xr, const f16* __restrict__ Wk,
    const float* __restrict__ bk, f16* __restrict__ Ko,
    const f16* __restrict__ y,  const f16* __restrict__ Wv,
    const float* __restrict__ bv, f16* __restrict__ Vo)
{
    extern __shared__ char smc[];
    const int bm = blockIdx.y * 128;
    const int bn = blockIdx.x * 128;
    if (blockIdx.z == 0) {
        gemm_body(smc, y, Wv, bv, nullptr, Vo, NI_,
                  (size_t)M_ * C_, (size_t)C_ * C_, 1, 1.0f, bm, bn);
    } else if (blockIdx.z == 1) {
        gemm_body(smc, xq, Wq, bq, nullptr, Qo, 1, 0, 0, 1, 0.125f, bm, bn);
    } else {
        gemm_body(smc, xr, Wk, bk, nullptr, Ko, 1, 0, 0, 1, 1.0f, bm, bn);
    }
}

// ============================================================================
// Flash attention: single-fp16 mma, register softmax, wm prefetched before
// the QK mma block (latency hidden under mma), 3-stage KV, 2 CTAs/SM.
// Q is pre-scaled by 1/sqrt(hd) -> logits come out of mma ready for masking.
// ============================================================================
#define FQ 128
#define FS 64
#define FSTR 72
#define OFF_Q 0
#define OFF_BUF 18432
#define KV_BUF_BYTES 18432
#define FLASH_SMEM (OFF_BUF + 3 * KV_BUF_BYTES)    // 73728 -> 2 CTAs/SM

__device__ __forceinline__ void flash_load_kv(
    uint32_t bb, const f16* __restrict__ K, const f16* __restrict__ V,
    int b, int h, int s0, int tid)
{
    #pragma unroll
    for (int v = 0; v < 2; v++) {
        int idx = tid + v * 256;
        int r = idx >> 3, c = idx & 7;
        size_t go = (size_t)(b * T_ + s0 + r) * C_ + h * HD_ + c * 8;
        uint32_t so = bb + r * (FSTR * 2) + c * 16;
        CP_ASYNC16(so,        K + go);
        CP_ASYNC16(so + 9216, V + go);
    }
}

__global__ __launch_bounds__(256, 2) void flash_mma_kernel(
    const f16* __restrict__ Q, const f16* __restrict__ K,
    const f16* __restrict__ V, const float* __restrict__ wm,
    f16* __restrict__ O)
{
    extern __shared__ char smc[];
    const uint32_t smb = smem_u32(smc);

    const int bh  = blockIdx.x;
    const int b   = bh >> 4;
    const int h   = bh & 15;
    const int t10 = blockIdx.y * FQ;
    const int tid = threadIdx.x;
    const int lane = tid & 31;
    const int wid = tid >> 5;
    const int m0 = wid * 16;
    const int g  = lane >> 2;
    const int c2 = (lane & 3) * 2;

    const int qr0 = t10 + m0 + g;
    const int qr1 = qr0 + 8;
    const float* wrow0 = &wm[(size_t)(b * T_ + qr0) * T_];
    const float* wrow1 = &wm[(size_t)(b * T_ + qr1) * T_];

    // ---- load Q tile (single f16, pre-scaled) ----
    #pragma unroll
    for (int v = 0; v < 4; v++) {
        int idx = tid + v * 256;
        int r = idx >> 3, c = idx & 7;
        size_t go = (size_t)(b * T_ + t10 + r) * C_ + h * HD_ + c * 8;
        uint32_t so = smb + OFF_Q + r * (FSTR * 2) + c * 16;
        CP_ASYNC16(so, Q + go);
    }
    CP_COMMIT();
    flash_load_kv(smb + OFF_BUF, K, V, b, h, 0, tid);
    CP_COMMIT();
    flash_load_kv(smb + OFF_BUF + KV_BUF_BYTES, K, V, b, h, FS, tid);
    CP_COMMIT();

    float mstat0 = -3.0e38f, mstat1 = -3.0e38f;
    float lstat0 = 0.f, lstat1 = 0.f;

    float oacc[8][4];
    #pragma unroll
    for (int ni = 0; ni < 8; ni++)
        #pragma unroll
        for (int r = 0; r < 4; r++) oacc[ni][r] = 0.f;

    const int NITER = T_ / FS;           // 32

    for (int it = 0; it < NITER; it++) {
        if (it + 1 < NITER) { CP_WAIT(1); } else { CP_WAIT(0); }
        __syncthreads();
        if (it + 2 < NITER) {
            flash_load_kv(smb + OFF_BUF + ((it + 2) % 3) * KV_BUF_BYTES,
                          K, V, b, h, (it + 2) * FS, tid);
            CP_COMMIT();
        }

        const int s0 = it * FS;
        const uint32_t bb = smb + OFF_BUF + (it % 3) * KV_BUF_BYTES;
        const uint32_t smK = bb;
        const uint32_t smV = bb + 9216;

        // ---- prefetch wm for this tile (latency hidden under QK mma) ----
        float wreg[8][4];
        #pragma unroll
        for (int ni = 0; ni < 8; ni++) {
            int s = s0 + ni * 8 + c2;
            float2 w0 = *(const float2*)&wrow0[s];
            float2 w1 = *(const float2*)&wrow1[s];
            wreg[ni][0] = w0.x; wreg[ni][1] = w0.y;
            wreg[ni][2] = w1.x; wreg[ni][3] = w1.y;
        }

        // ---- S = Q K^T  (Q pre-scaled by 1/sqrt(hd)) ----
        float sacc[8][4];
        #pragma unroll
        for (int ni = 0; ni < 8; ni++)
            #pragma unroll
            for (int r = 0; r < 4; r++) sacc[ni][r] = 0.f;

        #pragma unroll
        for (int ks = 0; ks < 4; ks++) {
            const int k0 = ks * 16;
            uint32_t qf[4];
            uint32_t aoff = (uint32_t)OFF_Q +
                ((m0 + (lane & 15)) * FSTR + k0 + ((lane >> 4) << 3)) * 2;
            LDSM_X4(qf[0], qf[1], qf[2], qf[3], smb + aoff);
            #pragma unroll
            for (int nj = 0; nj < 4; nj++) {
                uint32_t kh4[4];
                uint32_t boff = ((nj * 16 + (lane & 7) + ((lane >> 4) << 3)) * FSTR +
                                 k0 + ((lane >> 3) & 1) * 8) * 2;
                LDSM_X4(kh4[0], kh4[1], kh4[2], kh4[3], smK + boff);
                MMA16816(sacc[nj * 2],     qf, kh4[0], kh4[1]);
                MMA16816(sacc[nj * 2 + 1], qf, kh4[2], kh4[3]);
            }
        }

        // ---- mask via wm sign (no scale needed) ----
        #pragma unroll
        for (int ni = 0; ni < 8; ni++) {
            sacc[ni][0] = wreg[ni][0] > 0.f ? sacc[ni][0] : NEG_;
            sacc[ni][1] = wreg[ni][1] > 0.f ? sacc[ni][1] : NEG_;
            sacc[ni][2] = wreg[ni][2] > 0.f ? sacc[ni][2] : NEG_;
            sacc[ni][3] = wreg[ni][3] > 0.f ? sacc[ni][3] : NEG_;
        }

        // ---- row max ----
        float mx0 = -3.0e38f, mx1 = -3.0e38f;
        #pragma unroll
        for (int ni = 0; ni < 8; ni++) {
            mx0 = fmaxf(mx0, fmaxf(sacc[ni][0], sacc[ni][1]));
            mx1 = fmaxf(mx1, fmaxf(sacc[ni][2], sacc[ni][3]));
        }
        mx0 = fmaxf(mx0, __shfl_xor_sync(0xffffffff, mx0, 1));
        mx0 = fmaxf(mx0, __shfl_xor_sync(0xffffffff, mx0, 2));
        mx1 = fmaxf(mx1, __shfl_xor_sync(0xffffffff, mx1, 1));
        mx1 = fmaxf(mx1, __shfl_xor_sync(0xffffffff, mx1, 2));

        float mnew0 = fmaxf(mstat0, mx0);
        float mnew1 = fmaxf(mstat1, mx1);
        float fr0 = __expf(mstat0 - mnew0);
        float fr1 = __expf(mstat1 - mnew1);
        mstat0 = mnew0; mstat1 = mnew1;

        // ---- exp + row sum ----
        float sum0 = 0.f, sum1 = 0.f;
        #pragma unroll
        for (int ni = 0; ni < 8; ni++) {
            sacc[ni][0] = __expf(sacc[ni][0] - mnew0);
            sacc[ni][1] = __expf(sacc[ni][1] - mnew0);
            sacc[ni][2] = __expf(sacc[ni][2] - mnew1);
            sacc[ni][3] = __expf(sacc[ni][3] - mnew1);
            sum0 += sacc[ni][0] + sacc[ni][1];
            sum1 += sacc[ni][2] + sacc[ni][3];
        }
        sum0 += __shfl_xor_sync(0xffffffff, sum0, 1);
        sum0 += __shfl_xor_sync(0xffffffff, sum0, 2);
        sum1 += __shfl_xor_sync(0xffffffff, sum1, 1);
        sum1 += __shfl_xor_sync(0xffffffff, sum1, 2);
        lstat0 = lstat0 * fr0 + sum0;
        lstat1 = lstat1 * fr1 + sum1;

        // ---- numerator modulation + pack P fragments (single-cvt f16x2) ----
        uint32_t aP[4][4];
        #pragma unroll
        for (int j = 0; j < 4; j++) {
            #pragma unroll
            for (int half = 0; half < 2; half++) {
                int ni = 2 * j + half;
                float p00 = sacc[ni][0] * wreg[ni][0];
                float p01 = sacc[ni][1] * wreg[ni][1];
                float p10 = sacc[ni][2] * wreg[ni][2];
                float p11 = sacc[ni][3] * wreg[ni][3];
                aP[j][half * 2 + 0] = pack_h2(p00, p01);
                aP[j][half * 2 + 1] = pack_h2(p10, p11);
            }
        }

        // ---- rescale O, then O += P @ V ----
        #pragma unroll
        for (int ni = 0; ni < 8; ni++) {
            oacc[ni][0] *= fr0; oacc[ni][1] *= fr0;
            oacc[ni][2] *= fr1; oacc[ni][3] *= fr1;
        }
        #pragma unroll
        for (int j = 0; j < 4; j++) {
            #pragma unroll
            for (int nj = 0; nj < 4; nj++) {
                uint32_t vh4[4];
                uint32_t boff = ((j * 16 + (lane & 15)) * FSTR +
                                 (nj * 2 + ((lane >> 4) & 1)) * 8) * 2;
                LDSM_X4T(vh4[0], vh4[1], vh4[2], vh4[3], smV + boff);
                MMA16816(oacc[nj * 2],     aP[j], vh4[0], vh4[1]);
                MMA16816(oacc[nj * 2 + 1], aP[j], vh4[2], vh4[3]);
            }
        }
    }

    // ---- epilogue: /l, write single f16 ----
    {
        float inv0 = 1.0f / lstat0;
        float inv1 = 1.0f / lstat1;
        size_t row0 = (size_t)(b * T_ + qr0) * C_ + h * HD_;
        size_t row1 = (size_t)(b * T_ + qr1) * C_ + h * HD_;
        #pragma unroll
        for (int ni = 0; ni < 8; ni++) {
            int c = ni * 8 + c2;
            *(uint32_t*)&O[row0 + c] = pack_h2(oacc[ni][0] * inv0,
                                               oacc[ni][1] * inv0);
            *(uint32_t*)&O[row1 + c] = pack_h2(oacc[ni][2] * inv1,
                                               oacc[ni][3] * inv1);
        }
    }
}

// ============================================================================
// Launch
// ============================================================================
extern "C" void kernel_launch(void* const* d_in, const int* in_sizes, int n_in,
                              void* d_out, int out_size)
{
    const float* x_q  = (const float*)d_in[0];
    const float* x_r  = (const float*)d_in[1];
    const float* y    = (const float*)d_in[2];
    const int*   mask = (const int*)  d_in[3];
    const float* dist = (const float*)d_in[4];
    const float* Wq   = (const float*)d_in[5];
    const float* bq   = (const float*)d_in[6];
    const float* Wk   = (const float*)d_in[7];
    const float* bk   = (const float*)d_in[8];
    const float* Wv   = (const float*)d_in[9];
    const float* bv   = (const float*)d_in[10];
    const float* Wp   = (const float*)d_in[11];
    const float* bp   = (const float*)d_in[12];
    float* out = (float*)d_out;

    f16 *qb, *kb, *vb, *ob, *xq, *xr, *yb, *wq, *wk, *wv, *wp;
    float* wmp;
    cudaGetSymbolAddress((void**)&qb, g_Q);
    cudaGetSymbolAddress((void**)&kb, g_K);
    cudaGetSymbolAddress((void**)&vb, g_V);
    cudaGetSymbolAddress((void**)&ob, g_O);
    cudaGetSymbolAddress((void**)&xq, g_xq);
    cudaGetSymbolAddress((void**)&xr, g_xr);
    cudaGetSymbolAddress((void**)&yb, g_y);
    cudaGetSymbolAddress((void**)&wq, g_Wq);
    cudaGetSymbolAddress((void**)&wk, g_Wk);
    cudaGetSymbolAddress((void**)&wv, g_Wv);
    cudaGetSymbolAddress((void**)&wp, g_Wp);
    cudaGetSymbolAddress((void**)&wmp, g_wm);

    cudaFuncSetAttribute(gemm_mma_kernel,
                         cudaFuncAttributeMaxDynamicSharedMemorySize, GEMM_SMEM);
    cudaFuncSetAttribute(gemm_qkv_kernel,
                         cudaFuncAttributeMaxDynamicSharedMemorySize, GEMM_SMEM);
    cudaFuncSetAttribute(flash_mma_kernel,
                         cudaFuncAttributeMaxDynamicSharedMemorySize, FLASH_SMEM);

    // ---- one merged quant launch + wm ----
    quant_all_kernel<<<QBLOCKS, 256>>>(
        (const float4*)x_q, (const float4*)x_r, (const float4*)y,
        (const float4*)Wq, (const float4*)Wk, (const float4*)Wv,
        (const float4*)Wp,
        (uint2*)xq, (uint2*)xr, (uint2*)yb,
        (uint2*)wq, (uint2*)wk, (uint2*)wv, (uint2*)wp);
    {
        const int n4 = B_ * T_ * T_ / 4;
        wm_kernel<<<n4 / 1024, 256>>>((const int4*)mask, (const float4*)dist,
                                      (float4*)wmp, n4);
    }

    // ---- merged Q/K/V projections (V first via z=0) ----
    dim3 gblk(256);
    dim3 gqkv(C_ / 128, M_ / 128, 3);
    gemm_qkv_kernel<<<gqkv, gblk, GEMM_SMEM>>>(xq, wq, bq, qb,
                                               xr, wk, bk, kb,
                                               yb, wv, bv, vb);

    // ---- flash attention ----
    dim3 fgrd(B_ * H_, T_ / FQ);
    flash_mma_kernel<<<fgrd, 256, FLASH_SMEM>>>(qb, kb, vb, wmp, ob);

    // ---- out projection -> fp32 ----
    dim3 ggrd(C_ / 128, M_ / 128);
    gemm_mma_kernel<<<ggrd, gblk, GEMM_SMEM>>>(ob, wp, bp, out);
}